// round 10
// baseline (speedup 1.0000x reference)
#include <cuda_runtime.h>
#include <cstdint>
#include <math.h>

#define BB 16
#define TT 2048
#define CC 768
#define HH 128

// g_w: W^T, per weight [n=128][k=768], k permuted in 32-chunks (p32).
__device__ float g_w[3 * CC * HH];
// g_q, g_k: [token][128], row content permuted by P128. Q pre-scaled. tf32 bits.
// g_v: plain [token][128], tf32 bits.
__device__ float g_q[BB * TT * HH];
__device__ float g_k[BB * TT * HH];
__device__ float g_v[BB * TT * HH];

// ---------------------------------------------------------------------------
// helpers
// ---------------------------------------------------------------------------
__device__ __forceinline__ uint32_t f2tf(float f) {
    uint32_t u;
    asm("cvt.rna.tf32.f32 %0, %1;" : "=r"(u) : "f"(f));
    return u;
}

__device__ __forceinline__ void mma8(float* d, const uint32_t* a, const uint32_t* b) {
    asm volatile(
        "mma.sync.aligned.m16n8k8.row.col.f32.tf32.tf32.f32 "
        "{%0,%1,%2,%3}, {%4,%5,%6,%7}, {%8,%9}, {%0,%1,%2,%3};"
        : "+f"(d[0]), "+f"(d[1]), "+f"(d[2]), "+f"(d[3])
        : "r"(a[0]), "r"(a[1]), "r"(a[2]), "r"(a[3]),
          "r"(b[0]), "r"(b[1]));
}

__device__ __forceinline__ void cp_async16(uint32_t smem_dst, const void* gmem_src) {
    asm volatile("cp.async.cg.shared.global [%0], [%1], 16;"
                 :: "r"(smem_dst), "l"(gmem_src) : "memory");
}
__device__ __forceinline__ void cp_async_commit() {
    asm volatile("cp.async.commit_group;" ::: "memory");
}
__device__ __forceinline__ void cp_async_wait_all() {
    asm volatile("cp.async.wait_group 0;" ::: "memory");
}
__device__ __forceinline__ void cp_async_wait_1() {
    asm volatile("cp.async.wait_group 1;" ::: "memory");
}

__device__ __forceinline__ uint32_t smem_u32(const void* p) {
    uint32_t a;
    asm("{ .reg .u64 t; cvta.to.shared.u64 t, %1; cvt.u32.u64 %0, t; }"
        : "=r"(a) : "l"(p));
    return a;
}

// fragment-gather permutation for a 128-word row (Q/K):
// thread t=h&3 owns h; its words live contiguously at t*32.., XOR-swizzled
// in 16B chunks for bank-conflict-free LDS.128 at row stride 144.
__device__ __host__ __forceinline__ int P128(int h) {
    int th = h & 3;
    int q  = h >> 2;          // 0..31
    int jc = q >> 2;          // 0..7
    int r  = q & 3;
    return th * 32 + (((jc ^ th) & 7) << 2) + r;
}

// 32-chunk permutation for W rows: thread t's 8 words contiguous at t*8.
__device__ __forceinline__ int p32(int kl) {
    return (kl & 3) * 8 + (kl >> 2);
}

// ===========================================================================
// Kernel 0: build g_w = W^T with 32-chunk permuted k (Wq pre-scaled, rna).
// ===========================================================================
__global__ __launch_bounds__(256) void conv_w_kernel(
    const float* __restrict__ Wq,
    const float* __restrict__ Wk,
    const float* __restrict__ Wv)
{
    const int per = CC * HH;
    const float* Ws[3] = {Wq, Wk, Wv};
    for (int i = blockIdx.x * blockDim.x + threadIdx.x; i < 3 * per;
         i += gridDim.x * blockDim.x) {
        int w = i / per, rem = i - w * per;
        int k = rem / HH, n = rem - k * HH;     // read coalesced over n
        float s = (w == 0) ? 0.03608439182435161f : 1.0f;
        float v = Ws[w][(size_t)k * HH + n] * s;
        int pos = (k & ~31) + p32(k & 31);
        reinterpret_cast<uint32_t*>(g_w)[((size_t)w * HH + n) * CC + pos] = f2tf(v);
    }
}

// ===========================================================================
// Kernel 1: fused QKV projection, 2-stage cp.async pipeline.
// B-fragments via LDS.128 from permuted W^T tiles.
// ===========================================================================
#define NCH 24   // 768 / 32

#define AS_STRIDE 36
#define BSW_STRIDE 36                              // per-n-row: 32 words + pad
#define A_BUF (128 * AS_STRIDE)                    // 4608 words
#define B_ALL (3 * 128 * BSW_STRIDE)               // 13824 words
#define STAGE_WORDS (A_BUF + B_ALL)                // 18432 words
#define QKV_SMEM (2 * STAGE_WORDS * 4)             // 147456 B

__global__ __launch_bounds__(256) void qkv_fused_kernel(const float* __restrict__ x)
{
    extern __shared__ uint32_t sm_u[];
    const uint32_t sm_a = smem_u32(sm_u);

    const int tid  = threadIdx.x;
    const int lane = tid & 31;
    const int wid  = tid >> 5;
    const int g = lane >> 2;
    const int t = lane & 3;
    const int wr = wid & 3;
    const int wc = wid >> 2;
    const int m0 = blockIdx.x * 128;

    float acc[3][2][8][4];
    #pragma unroll
    for (int w = 0; w < 3; w++)
        #pragma unroll
        for (int mt = 0; mt < 2; mt++)
            #pragma unroll
            for (int nt = 0; nt < 8; nt++)
                #pragma unroll
                for (int e = 0; e < 4; e++) acc[w][mt][nt][e] = 0.0f;

    auto issue_stage = [&](int c, int buf) {
        const uint32_t base = sm_a + (uint32_t)buf * STAGE_WORDS * 4;
        // A: 128 rows x 32 raw fp32 = 1024 float4
        const float* xg = x + (size_t)m0 * CC + c * 32;
        #pragma unroll
        for (int p = 0; p < 4; p++) {
            int idx = tid + p * 256;
            int m = idx >> 3, k4 = (idx & 7) << 2;
            cp_async16(base + (uint32_t)(m * AS_STRIDE + k4) * 4,
                       xg + (size_t)m * CC + k4);
        }
        // B: 3 x 128 n-rows x 32 permuted words = 3072 float4
        #pragma unroll
        for (int p = 0; p < 12; p++) {
            int idx = tid + p * 256;
            int w = idx >> 10;
            int rem = idx & 1023;
            int n = rem >> 3, half = rem & 7;
            cp_async16(base + (uint32_t)(A_BUF + (w * 128 + n) * BSW_STRIDE + half * 4) * 4,
                       g_w + ((size_t)w * HH + n) * CC + c * 32 + half * 4);
        }
        cp_async_commit();
    };

    issue_stage(0, 0);

    for (int c = 0; c < NCH; c++) {
        const int buf = c & 1;
        __syncthreads();
        if (c + 1 < NCH) {
            issue_stage(c + 1, buf ^ 1);
            cp_async_wait_1();
        } else {
            cp_async_wait_all();
        }
        __syncthreads();

        const uint32_t* As = sm_u + buf * STAGE_WORDS;
        const uint32_t* Bs = As + A_BUF;

        #pragma unroll
        for (int jq = 0; jq < 2; jq++) {
            // A fragments for ks = 2*jq, 2*jq+1 (x unpermuted, scalar LDS)
            uint32_t afr[2][2][4];
            #pragma unroll
            for (int ksl = 0; ksl < 2; ksl++) {
                const int k = (jq * 2 + ksl) * 8 + t;
                #pragma unroll
                for (int mt = 0; mt < 2; mt++) {
                    const int rbase = wr * 32 + mt * 16;
                    afr[ksl][mt][0] = As[(rbase + g)     * AS_STRIDE + k];
                    afr[ksl][mt][1] = As[(rbase + g + 8) * AS_STRIDE + k];
                    afr[ksl][mt][2] = As[(rbase + g)     * AS_STRIDE + k + 4];
                    afr[ksl][mt][3] = As[(rbase + g + 8) * AS_STRIDE + k + 4];
                }
            }
            #pragma unroll
            for (int w = 0; w < 3; w++) {
                #pragma unroll
                for (int nt = 0; nt < 8; nt++) {
                    const int n = wc * 64 + nt * 8 + g;
                    uint4 bq = *reinterpret_cast<const uint4*>(
                        &Bs[(w * 128 + n) * BSW_STRIDE + t * 8 + jq * 4]);
                    uint32_t b0[2] = {bq.x, bq.y};
                    uint32_t b1[2] = {bq.z, bq.w};
                    mma8(acc[w][0][nt], afr[0][0], b0);
                    mma8(acc[w][1][nt], afr[0][1], b0);
                    mma8(acc[w][0][nt], afr[1][0], b1);
                    mma8(acc[w][1][nt], afr[1][1], b1);
                }
            }
        }
    }

    // ---- epilogue: Q,K permuted scalar stores; V plain float2 ----
    #pragma unroll
    for (int mt = 0; mt < 2; mt++) {
        const int r0 = m0 + wr * 32 + mt * 16 + g;
        #pragma unroll
        for (int nt = 0; nt < 8; nt++) {
            const int col = wc * 64 + nt * 8 + 2 * t;
            const int pa = P128(col), pb = P128(col + 1);
            // Q
            g_q[(size_t)r0 * HH + pa] = __uint_as_float(f2tf(acc[0][mt][nt][0]));
            g_q[(size_t)r0 * HH + pb] = __uint_as_float(f2tf(acc[0][mt][nt][1]));
            g_q[(size_t)(r0 + 8) * HH + pa] = __uint_as_float(f2tf(acc[0][mt][nt][2]));
            g_q[(size_t)(r0 + 8) * HH + pb] = __uint_as_float(f2tf(acc[0][mt][nt][3]));
            // K
            g_k[(size_t)r0 * HH + pa] = __uint_as_float(f2tf(acc[1][mt][nt][0]));
            g_k[(size_t)r0 * HH + pb] = __uint_as_float(f2tf(acc[1][mt][nt][1]));
            g_k[(size_t)(r0 + 8) * HH + pa] = __uint_as_float(f2tf(acc[1][mt][nt][2]));
            g_k[(size_t)(r0 + 8) * HH + pb] = __uint_as_float(f2tf(acc[1][mt][nt][3]));
            // V plain
            *reinterpret_cast<float2*>(&g_v[(size_t)r0 * HH + col]) =
                make_float2(__uint_as_float(f2tf(acc[2][mt][nt][0])),
                            __uint_as_float(f2tf(acc[2][mt][nt][1])));
            *reinterpret_cast<float2*>(&g_v[(size_t)(r0 + 8) * HH + col]) =
                make_float2(__uint_as_float(f2tf(acc[2][mt][nt][2])),
                            __uint_as_float(f2tf(acc[2][mt][nt][3])));
        }
    }
}

// ===========================================================================
// Kernel 2: register-resident causal flash attention, cp.async pipeline.
// K/Q rows permuted (P128) -> b/a fragments via LDS.128. V plain.
// ===========================================================================
#define KS_STRIDE 144
#define VS_STRIDE 136
#define ATTN_SMEM ((64 * KS_STRIDE + 64 * VS_STRIDE) * 4)   // 71680 B

__global__ __launch_bounds__(128, 2) void attn_fa2_kernel(float* __restrict__ out)
{
    extern __shared__ float smf[];
    float* Ks = smf;                     // [64][144]  permuted rows
    float* Vs = Ks + 64 * KS_STRIDE;     // [64][136]  (also Q staging)
    uint32_t* Ksu = reinterpret_cast<uint32_t*>(Ks);
    uint32_t* Vsu = reinterpret_cast<uint32_t*>(Vs);
    const uint32_t Ks_a = smem_u32(Ks);
    const uint32_t Vs_a = smem_u32(Vs);

    const int b  = blockIdx.y;
    const int qt = (int)gridDim.x - 1 - (int)blockIdx.x;
    const int q0 = qt * 64;
    const int tid  = threadIdx.x;
    const int wid  = tid >> 5;
    const int lane = tid & 31;
    const int g = lane >> 2;
    const int t = lane & 3;

    const int r0l = wid * 16 + g;
    const int r1l = r0l + 8;

    const float* kbase = g_k + (size_t)b * TT * HH;
    const float* vbase = g_v + (size_t)b * TT * HH;

    // ---- prologue: start K[0]; stage Q (permuted rows) through Vs ----
    {
        const float* kg = kbase;
        #pragma unroll
        for (int p = 0; p < 16; p++) {
            int idx = tid + p * 128;
            int r = idx >> 5, c = (idx & 31) << 2;
            cp_async16(Ks_a + (uint32_t)(r * KS_STRIDE + c) * 4,
                       kg + (size_t)r * HH + c);
        }
        cp_async_commit();
    }
    {
        const float* qg = g_q + ((size_t)b * TT + q0) * HH;
        #pragma unroll
        for (int p = 0; p < 16; p++) {
            int idx = tid + p * 128;
            int r = idx >> 5, c4 = (idx & 31) << 2;
            *reinterpret_cast<float4*>(&Vs[r * VS_STRIDE + c4]) =
                *reinterpret_cast<const float4*>(&qg[(size_t)r * HH + c4]);
        }
    }
    __syncthreads();

    // Q fragments from permuted rows: one LDS.128 covers 2 k-steps per row.
    uint32_t qfr[16][4];
    #pragma unroll
    for (int jc = 0; jc < 8; jc++) {
        const int off = t * 32 + (((jc ^ t) & 7) << 2);
        uint4 a0 = *reinterpret_cast<const uint4*>(&Vsu[r0l * VS_STRIDE + off]);
        uint4 a1 = *reinterpret_cast<const uint4*>(&Vsu[r1l * VS_STRIDE + off]);
        qfr[2 * jc][0]     = a0.x;  qfr[2 * jc][2]     = a0.y;
        qfr[2 * jc + 1][0] = a0.z;  qfr[2 * jc + 1][2] = a0.w;
        qfr[2 * jc][1]     = a1.x;  qfr[2 * jc][3]     = a1.y;
        qfr[2 * jc + 1][1] = a1.z;  qfr[2 * jc + 1][3] = a1.w;
    }

    float m0 = -INFINITY, m1 = -INFINITY, l0 = 0.0f, l1 = 0.0f;
    float oacc[16][4];
    #pragma unroll
    for (int nt = 0; nt < 16; nt++)
        #pragma unroll
        for (int e = 0; e < 4; e++) oacc[nt][e] = 0.0f;

    const uint32_t srcA = (lane & 28) | (t >> 1);
    const uint32_t srcB = srcA + 2;

    const int nkt = qt + 1;
    for (int kt = 0; kt < nkt; kt++) {
        cp_async_wait_all();
        __syncthreads();

        // V[kt] load (overlaps S compute)
        {
            const float* vg = vbase + (size_t)kt * 64 * HH;
            #pragma unroll
            for (int p = 0; p < 16; p++) {
                int idx = tid + p * 128;
                int r = idx >> 5, c = (idx & 31) << 2;
                cp_async16(Vs_a + (uint32_t)(r * VS_STRIDE + c) * 4,
                           vg + (size_t)r * HH + c);
            }
            cp_async_commit();
        }

        // ---- S = Q K^T : b-fragments via LDS.128 from permuted K rows ----
        float sacc[8][4];
        #pragma unroll
        for (int nt = 0; nt < 8; nt++)
            #pragma unroll
            for (int e = 0; e < 4; e++) sacc[nt][e] = 0.0f;

        #pragma unroll
        for (int nt = 0; nt < 8; nt++) {
            const uint32_t* Kn = Ksu + (nt * 8 + g) * KS_STRIDE + t * 32;
            #pragma unroll
            for (int jc2 = 0; jc2 < 4; jc2++) {
                uint4 b0 = *reinterpret_cast<const uint4*>(
                    &Kn[(((2 * jc2) ^ t) & 7) << 2]);
                uint4 b1 = *reinterpret_cast<const uint4*>(
                    &Kn[(((2 * jc2 + 1) ^ t) & 7) << 2]);
                uint32_t p0[2] = {b0.x, b0.y};
                uint32_t p1[2] = {b0.z, b0.w};
                uint32_t p2[2] = {b1.x, b1.y};
                uint32_t p3[2] = {b1.z, b1.w};
                mma8(sacc[nt], qfr[4 * jc2],     p0);
                mma8(sacc[nt], qfr[4 * jc2 + 1], p1);
                mma8(sacc[nt], qfr[4 * jc2 + 2], p2);
                mma8(sacc[nt], qfr[4 * jc2 + 3], p3);
            }
        }

        if (kt == qt) {
            #pragma unroll
            for (int nt = 0; nt < 8; nt++) {
                const int cl = nt * 8 + 2 * t;
                if (cl     > r0l) sacc[nt][0] = -INFINITY;
                if (cl + 1 > r0l) sacc[nt][1] = -INFINITY;
                if (cl     > r1l) sacc[nt][2] = -INFINITY;
                if (cl + 1 > r1l) sacc[nt][3] = -INFINITY;
            }
        }

        float mx0 = -INFINITY, mx1 = -INFINITY;
        #pragma unroll
        for (int nt = 0; nt < 8; nt++) {
            mx0 = fmaxf(mx0, fmaxf(sacc[nt][0], sacc[nt][1]));
            mx1 = fmaxf(mx1, fmaxf(sacc[nt][2], sacc[nt][3]));
        }
        mx0 = fmaxf(mx0, __shfl_xor_sync(0xffffffffu, mx0, 1));
        mx0 = fmaxf(mx0, __shfl_xor_sync(0xffffffffu, mx0, 2));
        mx1 = fmaxf(mx1, __shfl_xor_sync(0xffffffffu, mx1, 1));
        mx1 = fmaxf(mx1, __shfl_xor_sync(0xffffffffu, mx1, 2));

        const float m0n = fmaxf(m0, mx0);
        const float m1n = fmaxf(m1, mx1);
        const float c0 = __expf(m0 - m0n);
        const float c1 = __expf(m1 - m1n);

        float s0 = 0.0f, s1 = 0.0f;
        #pragma unroll
        for (int nt = 0; nt < 8; nt++) {
            sacc[nt][0] = __expf(sacc[nt][0] - m0n);
            sacc[nt][1] = __expf(sacc[nt][1] - m0n);
            sacc[nt][2] = __expf(sacc[nt][2] - m1n);
            sacc[nt][3] = __expf(sacc[nt][3] - m1n);
            s0 += sacc[nt][0] + sacc[nt][1];
            s1 += sacc[nt][2] + sacc[nt][3];
        }
        s0 += __shfl_xor_sync(0xffffffffu, s0, 1);
        s0 += __shfl_xor_sync(0xffffffffu, s0, 2);
        s1 += __shfl_xor_sync(0xffffffffu, s1, 1);
        s1 += __shfl_xor_sync(0xffffffffu, s1, 2);

        l0 = l0 * c0 + s0;
        l1 = l1 * c1 + s1;
        m0 = m0n;
        m1 = m1n;

        #pragma unroll
        for (int nt = 0; nt < 16; nt++) {
            oacc[nt][0] *= c0; oacc[nt][1] *= c0;
            oacc[nt][2] *= c1; oacc[nt][3] *= c1;
        }

        cp_async_wait_all();
        __syncthreads();

        if (kt + 1 < nkt) {
            const float* kg = kbase + (size_t)(kt + 1) * 64 * HH;
            #pragma unroll
            for (int p = 0; p < 16; p++) {
                int idx = tid + p * 128;
                int r = idx >> 5, c = (idx & 31) << 2;
                cp_async16(Ks_a + (uint32_t)(r * KS_STRIDE + c) * 4,
                           kg + (size_t)r * HH + c);
            }
            cp_async_commit();
        }

        // ---- O += P V (unchanged) ----
        #pragma unroll
        for (int kk = 0; kk < 8; kk++) {
            float v0 = __shfl_sync(0xffffffffu, sacc[kk][0], srcA);
            float v1 = __shfl_sync(0xffffffffu, sacc[kk][1], srcA);
            float v2 = __shfl_sync(0xffffffffu, sacc[kk][2], srcA);
            float v3 = __shfl_sync(0xffffffffu, sacc[kk][3], srcA);
            float w0 = __shfl_sync(0xffffffffu, sacc[kk][0], srcB);
            float w1 = __shfl_sync(0xffffffffu, sacc[kk][1], srcB);
            float w2 = __shfl_sync(0xffffffffu, sacc[kk][2], srcB);
            float w3 = __shfl_sync(0xffffffffu, sacc[kk][3], srcB);
            uint32_t afr[4];
            afr[0] = f2tf((t & 1) ? v1 : v0);
            afr[1] = f2tf((t & 1) ? v3 : v2);
            afr[2] = f2tf((t & 1) ? w1 : w0);
            afr[3] = f2tf((t & 1) ? w3 : w2);

            const int k = kk * 8 + t;
            #pragma unroll
            for (int nt = 0; nt < 16; nt++) {
                const int n = nt * 8 + g;
                uint32_t bfr[2];
                bfr[0] = Vsu[k * VS_STRIDE + n];
                bfr[1] = Vsu[(k + 4) * VS_STRIDE + n];
                mma8(oacc[nt], afr, bfr);
            }
        }
    }

    const float inv0 = 1.0f / l0;
    const float inv1 = 1.0f / l1;
    float* og = out + ((size_t)b * TT + q0) * HH;
    #pragma unroll
    for (int nt = 0; nt < 16; nt++) {
        const int col = nt * 8 + 2 * t;
        *reinterpret_cast<float2*>(&og[(size_t)r0l * HH + col]) =
            make_float2(oacc[nt][0] * inv0, oacc[nt][1] * inv0);
        *reinterpret_cast<float2*>(&og[(size_t)r1l * HH + col]) =
            make_float2(oacc[nt][2] * inv1, oacc[nt][3] * inv1);
    }
}

// ===========================================================================
// Launch
// ===========================================================================
extern "C" void kernel_launch(void* const* d_in, const int* in_sizes, int n_in,
                              void* d_out, int out_size)
{
    const float* x  = (const float*)d_in[0];
    const float* Wq = (const float*)d_in[1];
    const float* Wk = (const float*)d_in[2];
    const float* Wv = (const float*)d_in[3];
    float* out = (float*)d_out;

    cudaFuncSetAttribute(qkv_fused_kernel,
                         cudaFuncAttributeMaxDynamicSharedMemorySize, QKV_SMEM);
    cudaFuncSetAttribute(attn_fa2_kernel,
                         cudaFuncAttributeMaxDynamicSharedMemorySize, ATTN_SMEM);

    conv_w_kernel<<<96, 256>>>(Wq, Wk, Wv);
    qkv_fused_kernel<<<TT * BB / 128, 256, QKV_SMEM>>>(x);
    attn_fa2_kernel<<<dim3(TT / 64, BB), 128, ATTN_SMEM>>>(out);
}

// round 11
// speedup vs baseline: 1.0859x; 1.0859x over previous
#include <cuda_runtime.h>
#include <cstdint>
#include <math.h>

#define BB 16
#define TT 2048
#define CC 768
#define HH 128

// g_w: W^T, per weight [n=128][k=768], k permuted in 32-chunks (p32),
// tf32-rounded, Wq pre-scaled.
__device__ float g_w[3 * CC * HH];
// Projected Q, K, V: plain [token][128], tf32-rounded, Q pre-scaled.
__device__ float g_q[BB * TT * HH];
__device__ float g_k[BB * TT * HH];
__device__ float g_v[BB * TT * HH];

// ---------------------------------------------------------------------------
// helpers
// ---------------------------------------------------------------------------
__device__ __forceinline__ uint32_t f2tf(float f) {
    uint32_t u;
    asm("cvt.rna.tf32.f32 %0, %1;" : "=r"(u) : "f"(f));
    return u;
}

__device__ __forceinline__ void mma8(float* d, const uint32_t* a, const uint32_t* b) {
    asm volatile(
        "mma.sync.aligned.m16n8k8.row.col.f32.tf32.tf32.f32 "
        "{%0,%1,%2,%3}, {%4,%5,%6,%7}, {%8,%9}, {%0,%1,%2,%3};"
        : "+f"(d[0]), "+f"(d[1]), "+f"(d[2]), "+f"(d[3])
        : "r"(a[0]), "r"(a[1]), "r"(a[2]), "r"(a[3]),
          "r"(b[0]), "r"(b[1]));
}

__device__ __forceinline__ void cp_async16(uint32_t smem_dst, const void* gmem_src) {
    asm volatile("cp.async.cg.shared.global [%0], [%1], 16;"
                 :: "r"(smem_dst), "l"(gmem_src) : "memory");
}
__device__ __forceinline__ void cp_async_commit() {
    asm volatile("cp.async.commit_group;" ::: "memory");
}
__device__ __forceinline__ void cp_async_wait_all() {
    asm volatile("cp.async.wait_group 0;" ::: "memory");
}
__device__ __forceinline__ void cp_async_wait_1() {
    asm volatile("cp.async.wait_group 1;" ::: "memory");
}

__device__ __forceinline__ uint32_t smem_u32(const void* p) {
    uint32_t a;
    asm("{ .reg .u64 t; cvta.to.shared.u64 t, %1; cvt.u32.u64 %0, t; }"
        : "=r"(a) : "l"(p));
    return a;
}

// 32-chunk permutation for W rows: thread t's 8 fragment words contiguous
// at t*8 within each 32-word chunk.
__device__ __forceinline__ int p32(int kl) {
    return (kl & 3) * 8 + (kl >> 2);
}

// ===========================================================================
// Kernel 0: build g_w = W^T with 32-chunk permuted k (Wq pre-scaled, rna).
// Loop order (w, n, k): 32 consecutive k fill exactly one permuted 32-word
// chunk -> stores 128B-coalesced. Reads are strided but W fits L2.
// ===========================================================================
__global__ __launch_bounds__(256) void conv_w_kernel(
    const float* __restrict__ Wq,
    const float* __restrict__ Wk,
    const float* __restrict__ Wv)
{
    const int per = CC * HH;
    const float* Ws[3] = {Wq, Wk, Wv};
    for (int i = blockIdx.x * blockDim.x + threadIdx.x; i < 3 * per;
         i += gridDim.x * blockDim.x) {
        int w = i / per, rem = i - w * per;
        int n = rem / CC, k = rem - n * CC;    // k fastest -> coalesced writes
        float s = (w == 0) ? 0.03608439182435161f : 1.0f;
        float v = Ws[w][(size_t)k * HH + n] * s;
        int pos = (k & ~31) + p32(k & 31);
        reinterpret_cast<uint32_t*>(g_w)[((size_t)w * HH + n) * CC + pos] = f2tf(v);
    }
}

// ===========================================================================
// Kernel 1: fused QKV projection, 2-stage cp.async pipeline.
// B-fragments via LDS.128 from permuted W^T tiles; plain coalesced epilogue.
// ===========================================================================
#define NCH 24   // 768 / 32

#define AS_STRIDE 36
#define BSW_STRIDE 36                              // per-n-row: 32 words + pad
#define A_BUF (128 * AS_STRIDE)                    // 4608 words
#define B_ALL (3 * 128 * BSW_STRIDE)               // 13824 words
#define STAGE_WORDS (A_BUF + B_ALL)                // 18432 words
#define QKV_SMEM (2 * STAGE_WORDS * 4)             // 147456 B

__global__ __launch_bounds__(256) void qkv_fused_kernel(const float* __restrict__ x)
{
    extern __shared__ uint32_t sm_u[];
    const uint32_t sm_a = smem_u32(sm_u);

    const int tid  = threadIdx.x;
    const int lane = tid & 31;
    const int wid  = tid >> 5;
    const int g = lane >> 2;
    const int t = lane & 3;
    const int wr = wid & 3;
    const int wc = wid >> 2;
    const int m0 = blockIdx.x * 128;

    float acc[3][2][8][4];
    #pragma unroll
    for (int w = 0; w < 3; w++)
        #pragma unroll
        for (int mt = 0; mt < 2; mt++)
            #pragma unroll
            for (int nt = 0; nt < 8; nt++)
                #pragma unroll
                for (int e = 0; e < 4; e++) acc[w][mt][nt][e] = 0.0f;

    auto issue_stage = [&](int c, int buf) {
        const uint32_t base = sm_a + (uint32_t)buf * STAGE_WORDS * 4;
        // A: 128 rows x 32 raw fp32 (HW truncates to tf32 in mma)
        const float* xg = x + (size_t)m0 * CC + c * 32;
        #pragma unroll
        for (int p = 0; p < 4; p++) {
            int idx = tid + p * 256;
            int m = idx >> 3, k4 = (idx & 7) << 2;
            cp_async16(base + (uint32_t)(m * AS_STRIDE + k4) * 4,
                       xg + (size_t)m * CC + k4);
        }
        // B: 3 x 128 n-rows x 32 permuted words
        #pragma unroll
        for (int p = 0; p < 12; p++) {
            int idx = tid + p * 256;
            int w = idx >> 10;
            int rem = idx & 1023;
            int n = rem >> 3, half = rem & 7;
            cp_async16(base + (uint32_t)(A_BUF + (w * 128 + n) * BSW_STRIDE + half * 4) * 4,
                       g_w + ((size_t)w * HH + n) * CC + c * 32 + half * 4);
        }
        cp_async_commit();
    };

    issue_stage(0, 0);

    for (int c = 0; c < NCH; c++) {
        const int buf = c & 1;
        __syncthreads();
        if (c + 1 < NCH) {
            issue_stage(c + 1, buf ^ 1);
            cp_async_wait_1();
        } else {
            cp_async_wait_all();
        }
        __syncthreads();

        const uint32_t* As = sm_u + buf * STAGE_WORDS;
        const uint32_t* Bs = As + A_BUF;

        #pragma unroll
        for (int jq = 0; jq < 2; jq++) {
            uint32_t afr[2][2][4];
            #pragma unroll
            for (int ksl = 0; ksl < 2; ksl++) {
                const int k = (jq * 2 + ksl) * 8 + t;
                #pragma unroll
                for (int mt = 0; mt < 2; mt++) {
                    const int rbase = wr * 32 + mt * 16;
                    afr[ksl][mt][0] = As[(rbase + g)     * AS_STRIDE + k];
                    afr[ksl][mt][1] = As[(rbase + g + 8) * AS_STRIDE + k];
                    afr[ksl][mt][2] = As[(rbase + g)     * AS_STRIDE + k + 4];
                    afr[ksl][mt][3] = As[(rbase + g + 8) * AS_STRIDE + k + 4];
                }
            }
            #pragma unroll
            for (int w = 0; w < 3; w++) {
                #pragma unroll
                for (int nt = 0; nt < 8; nt++) {
                    const int n = wc * 64 + nt * 8 + g;
                    uint4 bq = *reinterpret_cast<const uint4*>(
                        &Bs[(w * 128 + n) * BSW_STRIDE + t * 8 + jq * 4]);
                    uint32_t b0[2] = {bq.x, bq.y};
                    uint32_t b1[2] = {bq.z, bq.w};
                    mma8(acc[w][0][nt], afr[0][0], b0);
                    mma8(acc[w][1][nt], afr[0][1], b0);
                    mma8(acc[w][0][nt], afr[1][0], b1);
                    mma8(acc[w][1][nt], afr[1][1], b1);
                }
            }
        }
    }

    // ---- epilogue: plain coalesced float2 stores of tf32-rounded bits ----
    float* outs[3] = {g_q, g_k, g_v};
    #pragma unroll
    for (int w = 0; w < 3; w++) {
        float* outw = outs[w];
        #pragma unroll
        for (int mt = 0; mt < 2; mt++) {
            int r0 = m0 + wr * 32 + mt * 16 + g;
            #pragma unroll
            for (int nt = 0; nt < 8; nt++) {
                int col = wc * 64 + nt * 8 + 2 * t;
                *reinterpret_cast<float2*>(&outw[(size_t)r0 * HH + col]) =
                    make_float2(__uint_as_float(f2tf(acc[w][mt][nt][0])),
                                __uint_as_float(f2tf(acc[w][mt][nt][1])));
                *reinterpret_cast<float2*>(&outw[(size_t)(r0 + 8) * HH + col]) =
                    make_float2(__uint_as_float(f2tf(acc[w][mt][nt][2])),
                                __uint_as_float(f2tf(acc[w][mt][nt][3])));
            }
        }
    }
}

// ===========================================================================
// Kernel 2: register-resident causal flash attention with cp.async pipeline
// (exactly the R9 version — known good at ~172 us).
// ===========================================================================
#define KS_STRIDE 132
#define VS_STRIDE 136
#define ATTN_SMEM ((64 * KS_STRIDE + 64 * VS_STRIDE) * 4)   // 68608 B

__global__ __launch_bounds__(128, 2) void attn_fa2_kernel(float* __restrict__ out)
{
    extern __shared__ float smf[];
    float* Ks = smf;                     // [64][132]
    float* Vs = Ks + 64 * KS_STRIDE;     // [64][136]  (also Q staging)
    uint32_t* Ksu = reinterpret_cast<uint32_t*>(Ks);
    uint32_t* Vsu = reinterpret_cast<uint32_t*>(Vs);
    const uint32_t Ks_a = smem_u32(Ks);
    const uint32_t Vs_a = smem_u32(Vs);

    const int b  = blockIdx.y;
    const int qt = (int)gridDim.x - 1 - (int)blockIdx.x;
    const int q0 = qt * 64;
    const int tid  = threadIdx.x;
    const int wid  = tid >> 5;
    const int lane = tid & 31;
    const int g = lane >> 2;
    const int t = lane & 3;

    const int r0l = wid * 16 + g;
    const int r1l = r0l + 8;

    const float* kbase = g_k + (size_t)b * TT * HH;
    const float* vbase = g_v + (size_t)b * TT * HH;

    {
        const float* kg = kbase;
        #pragma unroll
        for (int p = 0; p < 16; p++) {
            int idx = tid + p * 128;
            int r = idx >> 5, c = (idx & 31) << 2;
            cp_async16(Ks_a + (uint32_t)(r * KS_STRIDE + c) * 4,
                       kg + (size_t)r * HH + c);
        }
        cp_async_commit();
    }
    {
        const float* qg = g_q + ((size_t)b * TT + q0) * HH;
        #pragma unroll
        for (int p = 0; p < 16; p++) {
            int idx = tid + p * 128;
            int r = idx >> 5, c4 = (idx & 31) << 2;
            *reinterpret_cast<float4*>(&Vs[r * VS_STRIDE + c4]) =
                *reinterpret_cast<const float4*>(&qg[(size_t)r * HH + c4]);
        }
    }
    __syncthreads();

    uint32_t qfr[16][4];
    #pragma unroll
    for (int ks = 0; ks < 16; ks++) {
        const int k = ks * 8 + t;
        qfr[ks][0] = Vsu[r0l * VS_STRIDE + k];
        qfr[ks][1] = Vsu[r1l * VS_STRIDE + k];
        qfr[ks][2] = Vsu[r0l * VS_STRIDE + k + 4];
        qfr[ks][3] = Vsu[r1l * VS_STRIDE + k + 4];
    }

    float m0 = -INFINITY, m1 = -INFINITY, l0 = 0.0f, l1 = 0.0f;
    float oacc[16][4];
    #pragma unroll
    for (int nt = 0; nt < 16; nt++)
        #pragma unroll
        for (int e = 0; e < 4; e++) oacc[nt][e] = 0.0f;

    const uint32_t srcA = (lane & 28) | (t >> 1);
    const uint32_t srcB = srcA + 2;

    const int nkt = qt + 1;
    for (int kt = 0; kt < nkt; kt++) {
        cp_async_wait_all();
        __syncthreads();

        {
            const float* vg = vbase + (size_t)kt * 64 * HH;
            #pragma unroll
            for (int p = 0; p < 16; p++) {
                int idx = tid + p * 128;
                int r = idx >> 5, c = (idx & 31) << 2;
                cp_async16(Vs_a + (uint32_t)(r * VS_STRIDE + c) * 4,
                           vg + (size_t)r * HH + c);
            }
            cp_async_commit();
        }

        float sacc[8][4];
        #pragma unroll
        for (int nt = 0; nt < 8; nt++)
            #pragma unroll
            for (int e = 0; e < 4; e++) sacc[nt][e] = 0.0f;

        #pragma unroll
        for (int ks = 0; ks < 16; ks++) {
            const int k = ks * 8 + t;
            #pragma unroll
            for (int nt = 0; nt < 8; nt++) {
                const int n = nt * 8 + g;
                uint32_t bfr[2];
                bfr[0] = Ksu[n * KS_STRIDE + k];
                bfr[1] = Ksu[n * KS_STRIDE + k + 4];
                mma8(sacc[nt], qfr[ks], bfr);
            }
        }

        if (kt == qt) {
            #pragma unroll
            for (int nt = 0; nt < 8; nt++) {
                const int cl = nt * 8 + 2 * t;
                if (cl     > r0l) sacc[nt][0] = -INFINITY;
                if (cl + 1 > r0l) sacc[nt][1] = -INFINITY;
                if (cl     > r1l) sacc[nt][2] = -INFINITY;
                if (cl + 1 > r1l) sacc[nt][3] = -INFINITY;
            }
        }

        float mx0 = -INFINITY, mx1 = -INFINITY;
        #pragma unroll
        for (int nt = 0; nt < 8; nt++) {
            mx0 = fmaxf(mx0, fmaxf(sacc[nt][0], sacc[nt][1]));
            mx1 = fmaxf(mx1, fmaxf(sacc[nt][2], sacc[nt][3]));
        }
        mx0 = fmaxf(mx0, __shfl_xor_sync(0xffffffffu, mx0, 1));
        mx0 = fmaxf(mx0, __shfl_xor_sync(0xffffffffu, mx0, 2));
        mx1 = fmaxf(mx1, __shfl_xor_sync(0xffffffffu, mx1, 1));
        mx1 = fmaxf(mx1, __shfl_xor_sync(0xffffffffu, mx1, 2));

        const float m0n = fmaxf(m0, mx0);
        const float m1n = fmaxf(m1, mx1);
        const float c0 = __expf(m0 - m0n);
        const float c1 = __expf(m1 - m1n);

        float s0 = 0.0f, s1 = 0.0f;
        #pragma unroll
        for (int nt = 0; nt < 8; nt++) {
            sacc[nt][0] = __expf(sacc[nt][0] - m0n);
            sacc[nt][1] = __expf(sacc[nt][1] - m0n);
            sacc[nt][2] = __expf(sacc[nt][2] - m1n);
            sacc[nt][3] = __expf(sacc[nt][3] - m1n);
            s0 += sacc[nt][0] + sacc[nt][1];
            s1 += sacc[nt][2] + sacc[nt][3];
        }
        s0 += __shfl_xor_sync(0xffffffffu, s0, 1);
        s0 += __shfl_xor_sync(0xffffffffu, s0, 2);
        s1 += __shfl_xor_sync(0xffffffffu, s1, 1);
        s1 += __shfl_xor_sync(0xffffffffu, s1, 2);

        l0 = l0 * c0 + s0;
        l1 = l1 * c1 + s1;
        m0 = m0n;
        m1 = m1n;

        #pragma unroll
        for (int nt = 0; nt < 16; nt++) {
            oacc[nt][0] *= c0; oacc[nt][1] *= c0;
            oacc[nt][2] *= c1; oacc[nt][3] *= c1;
        }

        cp_async_wait_all();
        __syncthreads();

        if (kt + 1 < nkt) {
            const float* kg = kbase + (size_t)(kt + 1) * 64 * HH;
            #pragma unroll
            for (int p = 0; p < 16; p++) {
                int idx = tid + p * 128;
                int r = idx >> 5, c = (idx & 31) << 2;
                cp_async16(Ks_a + (uint32_t)(r * KS_STRIDE + c) * 4,
                           kg + (size_t)r * HH + c);
            }
            cp_async_commit();
        }

        #pragma unroll
        for (int kk = 0; kk < 8; kk++) {
            float v0 = __shfl_sync(0xffffffffu, sacc[kk][0], srcA);
            float v1 = __shfl_sync(0xffffffffu, sacc[kk][1], srcA);
            float v2 = __shfl_sync(0xffffffffu, sacc[kk][2], srcA);
            float v3 = __shfl_sync(0xffffffffu, sacc[kk][3], srcA);
            float w0 = __shfl_sync(0xffffffffu, sacc[kk][0], srcB);
            float w1 = __shfl_sync(0xffffffffu, sacc[kk][1], srcB);
            float w2 = __shfl_sync(0xffffffffu, sacc[kk][2], srcB);
            float w3 = __shfl_sync(0xffffffffu, sacc[kk][3], srcB);
            uint32_t afr[4];
            afr[0] = f2tf((t & 1) ? v1 : v0);
            afr[1] = f2tf((t & 1) ? v3 : v2);
            afr[2] = f2tf((t & 1) ? w1 : w0);
            afr[3] = f2tf((t & 1) ? w3 : w2);

            const int k = kk * 8 + t;
            #pragma unroll
            for (int nt = 0; nt < 16; nt++) {
                const int n = nt * 8 + g;
                uint32_t bfr[2];
                bfr[0] = Vsu[k * VS_STRIDE + n];
                bfr[1] = Vsu[(k + 4) * VS_STRIDE + n];
                mma8(oacc[nt], afr, bfr);
            }
        }
    }

    const float inv0 = 1.0f / l0;
    const float inv1 = 1.0f / l1;
    float* og = out + ((size_t)b * TT + q0) * HH;
    #pragma unroll
    for (int nt = 0; nt < 16; nt++) {
        const int col = nt * 8 + 2 * t;
        *reinterpret_cast<float2*>(&og[(size_t)r0l * HH + col]) =
            make_float2(oacc[nt][0] * inv0, oacc[nt][1] * inv0);
        *reinterpret_cast<float2*>(&og[(size_t)r1l * HH + col]) =
            make_float2(oacc[nt][2] * inv1, oacc[nt][3] * inv1);
    }
}

// ===========================================================================
// Launch
// ===========================================================================
extern "C" void kernel_launch(void* const* d_in, const int* in_sizes, int n_in,
                              void* d_out, int out_size)
{
    const float* x  = (const float*)d_in[0];
    const float* Wq = (const float*)d_in[1];
    const float* Wk = (const float*)d_in[2];
    const float* Wv = (const float*)d_in[3];
    float* out = (float*)d_out;

    cudaFuncSetAttribute(qkv_fused_kernel,
                         cudaFuncAttributeMaxDynamicSharedMemorySize, QKV_SMEM);
    cudaFuncSetAttribute(attn_fa2_kernel,
                         cudaFuncAttributeMaxDynamicSharedMemorySize, ATTN_SMEM);

    conv_w_kernel<<<96, 256>>>(Wq, Wk, Wv);
    qkv_fused_kernel<<<TT * BB / 128, 256, QKV_SMEM>>>(x);
    attn_fa2_kernel<<<dim3(TT / 64, BB), 128, ATTN_SMEM>>>(out);
}

// round 12
// speedup vs baseline: 1.4546x; 1.3396x over previous
#include <cuda_runtime.h>
#include <cuda_fp16.h>
#include <cstdint>
#include <math.h>

#define BB 16
#define TT 2048
#define CC 768
#define HH 128

// g_w: W^T, per weight [n=128][k=768], k permuted in 32-chunks (p32),
// tf32-rounded, Wq pre-scaled.  (qkv mainloop input)
__device__ float g_w[3 * CC * HH];
// Attention inputs, fp16:
//   g_qh, g_kh: [b][t][h] row-major (Q pre-scaled)
//   g_vT:       [b][h][t] transposed
__device__ __half g_qh[BB * TT * HH];
__device__ __half g_kh[BB * TT * HH];
__device__ __half g_vT[BB * HH * TT];

// ---------------------------------------------------------------------------
// helpers
// ---------------------------------------------------------------------------
__device__ __forceinline__ uint32_t f2tf(float f) {
    uint32_t u;
    asm("cvt.rna.tf32.f32 %0, %1;" : "=r"(u) : "f"(f));
    return u;
}

// pack two floats into half2 register: bits[15:0]=lo, bits[31:16]=hi
__device__ __forceinline__ uint32_t packh2(float lo, float hi) {
    uint32_t d;
    asm("cvt.rn.f16x2.f32 %0, %1, %2;" : "=r"(d) : "f"(hi), "f"(lo));
    return d;
}

// D += A * B   (m16n8k8, tf32 inputs, fp32 accum) — qkv kernel
__device__ __forceinline__ void mma8(float* d, const uint32_t* a, const uint32_t* b) {
    asm volatile(
        "mma.sync.aligned.m16n8k8.row.col.f32.tf32.tf32.f32 "
        "{%0,%1,%2,%3}, {%4,%5,%6,%7}, {%8,%9}, {%0,%1,%2,%3};"
        : "+f"(d[0]), "+f"(d[1]), "+f"(d[2]), "+f"(d[3])
        : "r"(a[0]), "r"(a[1]), "r"(a[2]), "r"(a[3]),
          "r"(b[0]), "r"(b[1]));
}

// D += A * B   (m16n8k16, fp16 inputs, fp32 accum) — attention kernel
__device__ __forceinline__ void mma16(float* d, const uint32_t* a,
                                      uint32_t b0, uint32_t b1) {
    asm volatile(
        "mma.sync.aligned.m16n8k16.row.col.f32.f16.f16.f32 "
        "{%0,%1,%2,%3}, {%4,%5,%6,%7}, {%8,%9}, {%0,%1,%2,%3};"
        : "+f"(d[0]), "+f"(d[1]), "+f"(d[2]), "+f"(d[3])
        : "r"(a[0]), "r"(a[1]), "r"(a[2]), "r"(a[3]),
          "r"(b0), "r"(b1));
}

__device__ __forceinline__ void cp_async16(uint32_t smem_dst, const void* gmem_src) {
    asm volatile("cp.async.cg.shared.global [%0], [%1], 16;"
                 :: "r"(smem_dst), "l"(gmem_src) : "memory");
}
__device__ __forceinline__ void cp_async_commit() {
    asm volatile("cp.async.commit_group;" ::: "memory");
}
__device__ __forceinline__ void cp_async_wait_all() {
    asm volatile("cp.async.wait_group 0;" ::: "memory");
}
__device__ __forceinline__ void cp_async_wait_1() {
    asm volatile("cp.async.wait_group 1;" ::: "memory");
}

__device__ __forceinline__ uint32_t smem_u32(const void* p) {
    uint32_t a;
    asm("{ .reg .u64 t; cvta.to.shared.u64 t, %1; cvt.u32.u64 %0, t; }"
        : "=r"(a) : "l"(p));
    return a;
}

__device__ __forceinline__ int p32(int kl) {
    return (kl & 3) * 8 + (kl >> 2);
}

// ===========================================================================
// Kernel 0: build g_w = W^T with 32-chunk permuted k (Wq pre-scaled, rna).
// ===========================================================================
__global__ __launch_bounds__(256) void conv_w_kernel(
    const float* __restrict__ Wq,
    const float* __restrict__ Wk,
    const float* __restrict__ Wv)
{
    const int per = CC * HH;
    const float* Ws[3] = {Wq, Wk, Wv};
    for (int i = blockIdx.x * blockDim.x + threadIdx.x; i < 3 * per;
         i += gridDim.x * blockDim.x) {
        int w = i / per, rem = i - w * per;
        int n = rem / CC, k = rem - n * CC;    // k fastest -> coalesced writes
        float s = (w == 0) ? 0.03608439182435161f : 1.0f;
        float v = Ws[w][(size_t)k * HH + n] * s;
        int pos = (k & ~31) + p32(k & 31);
        reinterpret_cast<uint32_t*>(g_w)[((size_t)w * HH + n) * CC + pos] = f2tf(v);
    }
}

// ===========================================================================
// Kernel 1: fused QKV projection (tf32 mainloop, unchanged from R11).
// Epilogue now emits fp16: g_qh/g_kh row-major half2, g_vT transposed.
// ===========================================================================
#define NCH 24

#define AS_STRIDE 36
#define BSW_STRIDE 36
#define A_BUF (128 * AS_STRIDE)
#define B_ALL (3 * 128 * BSW_STRIDE)
#define STAGE_WORDS (A_BUF + B_ALL)
#define QKV_SMEM (2 * STAGE_WORDS * 4)

__global__ __launch_bounds__(256) void qkv_fused_kernel(const float* __restrict__ x)
{
    extern __shared__ uint32_t sm_u[];
    const uint32_t sm_a = smem_u32(sm_u);

    const int tid  = threadIdx.x;
    const int lane = tid & 31;
    const int wid  = tid >> 5;
    const int g = lane >> 2;
    const int t = lane & 3;
    const int wr = wid & 3;
    const int wc = wid >> 2;
    const int m0 = blockIdx.x * 128;

    float acc[3][2][8][4];
    #pragma unroll
    for (int w = 0; w < 3; w++)
        #pragma unroll
        for (int mt = 0; mt < 2; mt++)
            #pragma unroll
            for (int nt = 0; nt < 8; nt++)
                #pragma unroll
                for (int e = 0; e < 4; e++) acc[w][mt][nt][e] = 0.0f;

    auto issue_stage = [&](int c, int buf) {
        const uint32_t base = sm_a + (uint32_t)buf * STAGE_WORDS * 4;
        const float* xg = x + (size_t)m0 * CC + c * 32;
        #pragma unroll
        for (int p = 0; p < 4; p++) {
            int idx = tid + p * 256;
            int m = idx >> 3, k4 = (idx & 7) << 2;
            cp_async16(base + (uint32_t)(m * AS_STRIDE + k4) * 4,
                       xg + (size_t)m * CC + k4);
        }
        #pragma unroll
        for (int p = 0; p < 12; p++) {
            int idx = tid + p * 256;
            int w = idx >> 10;
            int rem = idx & 1023;
            int n = rem >> 3, half = rem & 7;
            cp_async16(base + (uint32_t)(A_BUF + (w * 128 + n) * BSW_STRIDE + half * 4) * 4,
                       g_w + ((size_t)w * HH + n) * CC + c * 32 + half * 4);
        }
        cp_async_commit();
    };

    issue_stage(0, 0);

    for (int c = 0; c < NCH; c++) {
        const int buf = c & 1;
        __syncthreads();
        if (c + 1 < NCH) {
            issue_stage(c + 1, buf ^ 1);
            cp_async_wait_1();
        } else {
            cp_async_wait_all();
        }
        __syncthreads();

        const uint32_t* As = sm_u + buf * STAGE_WORDS;
        const uint32_t* Bs = As + A_BUF;

        #pragma unroll
        for (int jq = 0; jq < 2; jq++) {
            uint32_t afr[2][2][4];
            #pragma unroll
            for (int ksl = 0; ksl < 2; ksl++) {
                const int k = (jq * 2 + ksl) * 8 + t;
                #pragma unroll
                for (int mt = 0; mt < 2; mt++) {
                    const int rbase = wr * 32 + mt * 16;
                    afr[ksl][mt][0] = As[(rbase + g)     * AS_STRIDE + k];
                    afr[ksl][mt][1] = As[(rbase + g + 8) * AS_STRIDE + k];
                    afr[ksl][mt][2] = As[(rbase + g)     * AS_STRIDE + k + 4];
                    afr[ksl][mt][3] = As[(rbase + g + 8) * AS_STRIDE + k + 4];
                }
            }
            #pragma unroll
            for (int w = 0; w < 3; w++) {
                #pragma unroll
                for (int nt = 0; nt < 8; nt++) {
                    const int n = wc * 64 + nt * 8 + g;
                    uint4 bq = *reinterpret_cast<const uint4*>(
                        &Bs[(w * 128 + n) * BSW_STRIDE + t * 8 + jq * 4]);
                    uint32_t b0[2] = {bq.x, bq.y};
                    uint32_t b1[2] = {bq.z, bq.w};
                    mma8(acc[w][0][nt], afr[0][0], b0);
                    mma8(acc[w][1][nt], afr[0][1], b0);
                    mma8(acc[w][0][nt], afr[1][0], b1);
                    mma8(acc[w][1][nt], afr[1][1], b1);
                }
            }
        }
    }

    // ---- epilogue: fp16 outputs ----
    __half* outs2[2] = {g_qh, g_kh};
    #pragma unroll
    for (int mt = 0; mt < 2; mt++) {
        const int r0 = m0 + wr * 32 + mt * 16 + g;
        const int bq = r0 >> 11;            // batch
        const int tp = r0 & 2047;           // token within batch
        #pragma unroll
        for (int nt = 0; nt < 8; nt++) {
            const int col = wc * 64 + nt * 8 + 2 * t;
            // Q, K: half2 stores (row-major)
            #pragma unroll
            for (int w = 0; w < 2; w++) {
                __half* outw = outs2[w];
                *reinterpret_cast<uint32_t*>(&outw[(size_t)r0 * HH + col]) =
                    packh2(acc[w][mt][nt][0], acc[w][mt][nt][1]);
                *reinterpret_cast<uint32_t*>(&outw[(size_t)(r0 + 8) * HH + col]) =
                    packh2(acc[w][mt][nt][2], acc[w][mt][nt][3]);
            }
            // V: transposed [b][h][t]
            const size_t vb = ((size_t)bq * HH + col) * TT;
            g_vT[vb + tp]          = __float2half_rn(acc[2][mt][nt][0]);
            g_vT[vb + TT + tp]     = __float2half_rn(acc[2][mt][nt][1]);
            g_vT[vb + tp + 8]      = __float2half_rn(acc[2][mt][nt][2]);
            g_vT[vb + TT + tp + 8] = __float2half_rn(acc[2][mt][nt][3]);
        }
    }
}

// ===========================================================================
// Kernel 2: fp16 register-resident causal flash attention, cp.async pipeline.
// K row-major [64][136]h; V^T [128][72]h; Q staged through V^T buffer.
// S->P fragment handoff needs NO shuffles (f16 C layout == A layout).
// ===========================================================================
#define KH_STRIDE 136   // halfs per K row (word bank = 4g+t -> conflict-free)
#define VT_STRIDE 72    // halfs per V^T row
#define ATTN_SMEM ((64 * KH_STRIDE + 128 * VT_STRIDE) * 2)   // 35840 B

__global__ __launch_bounds__(128, 2) void attn_fa2_kernel(float* __restrict__ out)
{
    extern __shared__ __half smh[];
    __half* Ksh = smh;                        // [64][136]
    __half* Vth = smh + 64 * KH_STRIDE;       // [128][72] V^T; also Q staging
    const uint32_t Ks_a = smem_u32(Ksh);
    const uint32_t Vt_a = smem_u32(Vth);
    const uint32_t* Ks32 = reinterpret_cast<const uint32_t*>(Ksh);
    const uint32_t* Vt32 = reinterpret_cast<const uint32_t*>(Vth);

    const int b  = blockIdx.y;
    const int qt = (int)gridDim.x - 1 - (int)blockIdx.x;   // heavy tiles first
    const int q0 = qt * 64;
    const int tid  = threadIdx.x;
    const int wid  = tid >> 5;
    const int lane = tid & 31;
    const int g = lane >> 2;
    const int t = lane & 3;

    const int r0l = wid * 16 + g;
    const int r1l = r0l + 8;

    const __half* kbase  = g_kh + (size_t)b * TT * HH;
    const __half* vtbase = g_vT + (size_t)b * HH * TT;

    // ---- prologue: start K[0]; stage Q (row-major, stride 136) into Vth ----
    {
        #pragma unroll
        for (int p = 0; p < 8; p++) {
            int idx = tid + p * 128;
            int r = idx >> 4, ch = idx & 15;
            cp_async16(Ks_a + (uint32_t)(r * KH_STRIDE + ch * 8) * 2,
                       kbase + (size_t)r * HH + ch * 8);
        }
        cp_async_commit();
    }
    {
        const __half* qg = g_qh + ((size_t)b * TT + q0) * HH;
        #pragma unroll
        for (int p = 0; p < 8; p++) {
            int idx = tid + p * 128;
            int r = idx >> 4, ch = idx & 15;
            *reinterpret_cast<uint4*>(&Vth[r * KH_STRIDE + ch * 8]) =
                *reinterpret_cast<const uint4*>(&qg[(size_t)r * HH + ch * 8]);
        }
    }
    __syncthreads();

    // Q fragments (m16n8k16 A): half2 pairs, register-resident for whole loop
    uint32_t qfr[8][4];
    #pragma unroll
    for (int ks = 0; ks < 8; ks++) {
        qfr[ks][0] = Vt32[68 * r0l + 8 * ks + t];
        qfr[ks][1] = Vt32[68 * r1l + 8 * ks + t];
        qfr[ks][2] = Vt32[68 * r0l + 8 * ks + t + 4];
        qfr[ks][3] = Vt32[68 * r1l + 8 * ks + t + 4];
    }

    float m0 = -INFINITY, m1 = -INFINITY, l0 = 0.0f, l1 = 0.0f;
    float oacc[16][4];
    #pragma unroll
    for (int nt = 0; nt < 16; nt++)
        #pragma unroll
        for (int e = 0; e < 4; e++) oacc[nt][e] = 0.0f;

    const int nkt = qt + 1;
    for (int kt = 0; kt < nkt; kt++) {
        // K[kt] arrived; qfr loaded / previous PV done with Vth
        cp_async_wait_all();
        __syncthreads();

        // ---- start V^T[kt] load (overlaps S compute) ----
        {
            #pragma unroll
            for (int p = 0; p < 8; p++) {
                int idx = tid + p * 128;
                int h = idx >> 3, ch = idx & 7;
                cp_async16(Vt_a + (uint32_t)(h * VT_STRIDE + ch * 8) * 2,
                           vtbase + (size_t)h * TT + kt * 64 + ch * 8);
            }
            cp_async_commit();
        }

        // ---- S = Q K^T ----
        float sacc[8][4];
        #pragma unroll
        for (int nt = 0; nt < 8; nt++)
            #pragma unroll
            for (int e = 0; e < 4; e++) sacc[nt][e] = 0.0f;

        #pragma unroll
        for (int ks = 0; ks < 8; ks++) {
            #pragma unroll
            for (int nt = 0; nt < 8; nt++) {
                const int n = nt * 8 + g;
                mma16(sacc[nt], qfr[ks],
                      Ks32[68 * n + 8 * ks + t],
                      Ks32[68 * n + 8 * ks + t + 4]);
            }
        }

        // ---- mask (diagonal tile) ----
        if (kt == qt) {
            #pragma unroll
            for (int nt = 0; nt < 8; nt++) {
                const int cl = nt * 8 + 2 * t;
                if (cl     > r0l) sacc[nt][0] = -INFINITY;
                if (cl + 1 > r0l) sacc[nt][1] = -INFINITY;
                if (cl     > r1l) sacc[nt][2] = -INFINITY;
                if (cl + 1 > r1l) sacc[nt][3] = -INFINITY;
            }
        }

        // ---- online softmax in registers ----
        float mx0 = -INFINITY, mx1 = -INFINITY;
        #pragma unroll
        for (int nt = 0; nt < 8; nt++) {
            mx0 = fmaxf(mx0, fmaxf(sacc[nt][0], sacc[nt][1]));
            mx1 = fmaxf(mx1, fmaxf(sacc[nt][2], sacc[nt][3]));
        }
        mx0 = fmaxf(mx0, __shfl_xor_sync(0xffffffffu, mx0, 1));
        mx0 = fmaxf(mx0, __shfl_xor_sync(0xffffffffu, mx0, 2));
        mx1 = fmaxf(mx1, __shfl_xor_sync(0xffffffffu, mx1, 1));
        mx1 = fmaxf(mx1, __shfl_xor_sync(0xffffffffu, mx1, 2));

        const float m0n = fmaxf(m0, mx0);
        const float m1n = fmaxf(m1, mx1);
        const float c0 = __expf(m0 - m0n);
        const float c1 = __expf(m1 - m1n);

        float s0 = 0.0f, s1 = 0.0f;
        #pragma unroll
        for (int nt = 0; nt < 8; nt++) {
            sacc[nt][0] = __expf(sacc[nt][0] - m0n);
            sacc[nt][1] = __expf(sacc[nt][1] - m0n);
            sacc[nt][2] = __expf(sacc[nt][2] - m1n);
            sacc[nt][3] = __expf(sacc[nt][3] - m1n);
            s0 += sacc[nt][0] + sacc[nt][1];
            s1 += sacc[nt][2] + sacc[nt][3];
        }
        s0 += __shfl_xor_sync(0xffffffffu, s0, 1);
        s0 += __shfl_xor_sync(0xffffffffu, s0, 2);
        s1 += __shfl_xor_sync(0xffffffffu, s1, 1);
        s1 += __shfl_xor_sync(0xffffffffu, s1, 2);

        l0 = l0 * c0 + s0;
        l1 = l1 * c1 + s1;
        m0 = m0n;
        m1 = m1n;

        #pragma unroll
        for (int nt = 0; nt < 16; nt++) {
            oacc[nt][0] *= c0; oacc[nt][1] *= c0;
            oacc[nt][2] *= c1; oacc[nt][3] *= c1;
        }

        // ---- V^T[kt] arrived; warps done reading K ----
        cp_async_wait_all();
        __syncthreads();

        // ---- start K[kt+1] load (overlaps PV compute) ----
        if (kt + 1 < nkt) {
            const __half* kg = kbase + (size_t)(kt + 1) * 64 * HH;
            #pragma unroll
            for (int p = 0; p < 8; p++) {
                int idx = tid + p * 128;
                int r = idx >> 4, ch = idx & 15;
                cp_async16(Ks_a + (uint32_t)(r * KH_STRIDE + ch * 8) * 2,
                           kg + (size_t)r * HH + ch * 8);
            }
            cp_async_commit();
        }

        // ---- O += P V : P packs directly into A-fragments (no shuffles) ----
        #pragma unroll
        for (int kk = 0; kk < 4; kk++) {
            uint32_t afr[4];
            afr[0] = packh2(sacc[2 * kk][0],     sacc[2 * kk][1]);
            afr[1] = packh2(sacc[2 * kk][2],     sacc[2 * kk][3]);
            afr[2] = packh2(sacc[2 * kk + 1][0], sacc[2 * kk + 1][1]);
            afr[3] = packh2(sacc[2 * kk + 1][2], sacc[2 * kk + 1][3]);
            #pragma unroll
            for (int nt = 0; nt < 16; nt++) {
                const int n = nt * 8 + g;
                mma16(oacc[nt], afr,
                      Vt32[36 * n + 8 * kk + t],
                      Vt32[36 * n + 8 * kk + t + 4]);
            }
        }
    }

    // ---- epilogue ----
    const float inv0 = 1.0f / l0;
    const float inv1 = 1.0f / l1;
    float* og = out + ((size_t)b * TT + q0) * HH;
    #pragma unroll
    for (int nt = 0; nt < 16; nt++) {
        const int col = nt * 8 + 2 * t;
        *reinterpret_cast<float2*>(&og[(size_t)r0l * HH + col]) =
            make_float2(oacc[nt][0] * inv0, oacc[nt][1] * inv0);
        *reinterpret_cast<float2*>(&og[(size_t)r1l * HH + col]) =
            make_float2(oacc[nt][2] * inv1, oacc[nt][3] * inv1);
    }
}

// ===========================================================================
// Launch
// ===========================================================================
extern "C" void kernel_launch(void* const* d_in, const int* in_sizes, int n_in,
                              void* d_out, int out_size)
{
    const float* x  = (const float*)d_in[0];
    const float* Wq = (const float*)d_in[1];
    const float* Wk = (const float*)d_in[2];
    const float* Wv = (const float*)d_in[3];
    float* out = (float*)d_out;

    cudaFuncSetAttribute(qkv_fused_kernel,
                         cudaFuncAttributeMaxDynamicSharedMemorySize, QKV_SMEM);
    cudaFuncSetAttribute(attn_fa2_kernel,
                         cudaFuncAttributeMaxDynamicSharedMemorySize, ATTN_SMEM);

    conv_w_kernel<<<96, 256>>>(Wq, Wk, Wv);
    qkv_fused_kernel<<<TT * BB / 128, 256, QKV_SMEM>>>(x);
    attn_fa2_kernel<<<dim3(TT / 64, BB), 128, ATTN_SMEM>>>(out);
}

// round 13
// speedup vs baseline: 1.6312x; 1.1214x over previous
#include <cuda_runtime.h>
#include <cuda_fp16.h>
#include <cstdint>
#include <math.h>

#define BB 16
#define TT 2048
#define CC 768
#define HH 128

// g_wh: W^T fp16, per weight [n=128][k=768], k permuted in 32-half chunks
// (pos16 word permutation), Wq pre-scaled.
__device__ __half g_wh[3 * CC * HH];
// Attention inputs, fp16:
//   g_qh, g_kh: [b][t][h] row-major (Q pre-scaled)
//   g_vT:       [b][h][t] transposed
__device__ __half g_qh[BB * TT * HH];
__device__ __half g_kh[BB * TT * HH];
__device__ __half g_vT[BB * HH * TT];

// ---------------------------------------------------------------------------
// helpers
// ---------------------------------------------------------------------------
// pack two floats into half2 register: bits[15:0]=lo, bits[31:16]=hi
__device__ __forceinline__ uint32_t packh2(float lo, float hi) {
    uint32_t d;
    asm("cvt.rn.f16x2.f32 %0, %1, %2;" : "=r"(d) : "f"(hi), "f"(lo));
    return d;
}

// D += A * B   (m16n8k16, fp16 inputs, fp32 accum)
__device__ __forceinline__ void mma16(float* d, const uint32_t* a,
                                      uint32_t b0, uint32_t b1) {
    asm volatile(
        "mma.sync.aligned.m16n8k16.row.col.f32.f16.f16.f32 "
        "{%0,%1,%2,%3}, {%4,%5,%6,%7}, {%8,%9}, {%0,%1,%2,%3};"
        : "+f"(d[0]), "+f"(d[1]), "+f"(d[2]), "+f"(d[3])
        : "r"(a[0]), "r"(a[1]), "r"(a[2]), "r"(a[3]),
          "r"(b0), "r"(b1));
}

__device__ __forceinline__ void cp_async16(uint32_t smem_dst, const void* gmem_src) {
    asm volatile("cp.async.cg.shared.global [%0], [%1], 16;"
                 :: "r"(smem_dst), "l"(gmem_src) : "memory");
}
__device__ __forceinline__ void cp_async_commit() {
    asm volatile("cp.async.commit_group;" ::: "memory");
}
__device__ __forceinline__ void cp_async_wait_all() {
    asm volatile("cp.async.wait_group 0;" ::: "memory");
}
__device__ __forceinline__ void cp_async_wait_1() {
    asm volatile("cp.async.wait_group 1;" ::: "memory");
}

__device__ __forceinline__ uint32_t smem_u32(const void* p) {
    uint32_t a;
    asm("{ .reg .u64 t; cvta.to.shared.u64 t, %1; cvt.u32.u64 %0, t; }"
        : "=r"(a) : "l"(p));
    return a;
}

// word permutation within a 16-word (32-half) k-chunk:
// thread t's 4 fragment words (2 k16-steps x {b0,b1}) land at 4t..4t+3.
__device__ __forceinline__ int pos16(int w) {
    return (w & 3) * 4 + ((w >> 3) & 1) * 2 + ((w >> 2) & 1);
}

// ===========================================================================
// Kernel 0: build g_wh = W^T fp16 with permuted k (Wq pre-scaled, rn).
// ===========================================================================
__global__ __launch_bounds__(256) void conv_w_kernel(
    const float* __restrict__ Wq,
    const float* __restrict__ Wk,
    const float* __restrict__ Wv)
{
    const int per = CC * HH;
    const float* Ws[3] = {Wq, Wk, Wv};
    for (int i = blockIdx.x * blockDim.x + threadIdx.x; i < 3 * per;
         i += gridDim.x * blockDim.x) {
        int w = i / per, rem = i - w * per;
        int n = rem / CC, k = rem - n * CC;    // k fastest
        float s = (w == 0) ? 0.03608439182435161f : 1.0f;
        float v = Ws[w][(size_t)k * HH + n] * s;
        int chunk = k >> 5, kl = k & 31;
        int word = kl >> 1, h = kl & 1;
        int pos = chunk * 32 + pos16(word) * 2 + h;
        g_wh[((size_t)w * HH + n) * CC + pos] = __float2half_rn(v);
    }
}

// ===========================================================================
// Kernel 1: fused QKV projection, fp16 m16n8k16 mainloop, 2-stage cp.async.
// A (raw fp32 x) staged per chunk; A-frags via LDS.64 + cvt.rn.f16x2.
// B-frags: one LDS.128 per (weight, n-tile) per 32-k chunk.
// ===========================================================================
#define NCH 24   // 768 / 32

#define AS_STRIDE 36                               // fp32 words per A row
#define BROW_WORDS 20                              // 16 data + 4 pad per n-row
#define A_BUF (128 * AS_STRIDE)                    // 4608 words
#define B_ALL (3 * 128 * BROW_WORDS)               // 7680 words
#define STAGE_WORDS (A_BUF + B_ALL)                // 12288 words
#define QKV_SMEM (2 * STAGE_WORDS * 4)             // 98304 B

__global__ __launch_bounds__(256) void qkv_fused_kernel(const float* __restrict__ x)
{
    extern __shared__ uint32_t sm_u[];
    const uint32_t sm_a = smem_u32(sm_u);

    const int tid  = threadIdx.x;
    const int lane = tid & 31;
    const int wid  = tid >> 5;
    const int g = lane >> 2;
    const int t = lane & 3;
    const int wr = wid & 3;
    const int wc = wid >> 2;
    const int m0 = blockIdx.x * 128;

    float acc[3][2][8][4];
    #pragma unroll
    for (int w = 0; w < 3; w++)
        #pragma unroll
        for (int mt = 0; mt < 2; mt++)
            #pragma unroll
            for (int nt = 0; nt < 8; nt++)
                #pragma unroll
                for (int e = 0; e < 4; e++) acc[w][mt][nt][e] = 0.0f;

    auto issue_stage = [&](int c, int buf) {
        const uint32_t base = sm_a + (uint32_t)buf * STAGE_WORDS * 4;
        // A: 128 rows x 32 fp32 = 1024 float4 chunks, 4/thread
        const float* xg = x + (size_t)m0 * CC + c * 32;
        #pragma unroll
        for (int p = 0; p < 4; p++) {
            int idx = tid + p * 256;
            int m = idx >> 3, k4 = (idx & 7) << 2;
            cp_async16(base + (uint32_t)(m * AS_STRIDE + k4) * 4,
                       xg + (size_t)m * CC + k4);
        }
        // B: 3 x 128 n-rows x 64B (16 words) = 1536 chunks, 6/thread
        #pragma unroll
        for (int p = 0; p < 6; p++) {
            int idx = tid + p * 256;
            int n_all = idx >> 2;           // 0..383
            int ch = idx & 3;               // 16B chunk within row
            cp_async16(base + (uint32_t)(A_BUF + n_all * BROW_WORDS + ch * 4) * 4,
                       g_wh + (size_t)n_all * CC + c * 32 + ch * 8);
        }
        cp_async_commit();
    };

    issue_stage(0, 0);

    for (int c = 0; c < NCH; c++) {
        const int buf = c & 1;
        __syncthreads();
        if (c + 1 < NCH) {
            issue_stage(c + 1, buf ^ 1);
            cp_async_wait_1();
        } else {
            cp_async_wait_all();
        }
        __syncthreads();

        const uint32_t* As = sm_u + buf * STAGE_WORDS;
        const uint32_t* Bs = As + A_BUF;
        const float2* A2 = reinterpret_cast<const float2*>(As);  // 18 f2/row

        // A fragments for both k16 steps (fp32 -> fp16 pack)
        uint32_t afr[2][2][4];     // [ks][mt][4]
        #pragma unroll
        for (int ks = 0; ks < 2; ks++) {
            #pragma unroll
            for (int mt = 0; mt < 2; mt++) {
                const int rb = wr * 32 + mt * 16;
                float2 p0 = A2[(rb + g)     * 18 + ks * 8 + t];
                float2 p1 = A2[(rb + g + 8) * 18 + ks * 8 + t];
                float2 p2 = A2[(rb + g)     * 18 + ks * 8 + t + 4];
                float2 p3 = A2[(rb + g + 8) * 18 + ks * 8 + t + 4];
                afr[ks][mt][0] = packh2(p0.x, p0.y);
                afr[ks][mt][1] = packh2(p1.x, p1.y);
                afr[ks][mt][2] = packh2(p2.x, p2.y);
                afr[ks][mt][3] = packh2(p3.x, p3.y);
            }
        }

        #pragma unroll
        for (int w = 0; w < 3; w++) {
            #pragma unroll
            for (int nt = 0; nt < 8; nt++) {
                const int n_all = w * 128 + wc * 64 + nt * 8 + g;
                uint4 bq = *reinterpret_cast<const uint4*>(
                    &Bs[n_all * BROW_WORDS + t * 4]);
                mma16(acc[w][0][nt], afr[0][0], bq.x, bq.y);
                mma16(acc[w][1][nt], afr[0][1], bq.x, bq.y);
                mma16(acc[w][0][nt], afr[1][0], bq.z, bq.w);
                mma16(acc[w][1][nt], afr[1][1], bq.z, bq.w);
            }
        }
    }

    // ---- epilogue: fp16 outputs (Q/K row-major half2, V transposed) ----
    __half* outs2[2] = {g_qh, g_kh};
    #pragma unroll
    for (int mt = 0; mt < 2; mt++) {
        const int r0 = m0 + wr * 32 + mt * 16 + g;
        const int bq = r0 >> 11;            // batch
        const int tp = r0 & 2047;           // token within batch
        #pragma unroll
        for (int nt = 0; nt < 8; nt++) {
            const int col = wc * 64 + nt * 8 + 2 * t;
            #pragma unroll
            for (int w = 0; w < 2; w++) {
                __half* outw = outs2[w];
                *reinterpret_cast<uint32_t*>(&outw[(size_t)r0 * HH + col]) =
                    packh2(acc[w][mt][nt][0], acc[w][mt][nt][1]);
                *reinterpret_cast<uint32_t*>(&outw[(size_t)(r0 + 8) * HH + col]) =
                    packh2(acc[w][mt][nt][2], acc[w][mt][nt][3]);
            }
            const size_t vb = ((size_t)bq * HH + col) * TT;
            g_vT[vb + tp]          = __float2half_rn(acc[2][mt][nt][0]);
            g_vT[vb + TT + tp]     = __float2half_rn(acc[2][mt][nt][1]);
            g_vT[vb + tp + 8]      = __float2half_rn(acc[2][mt][nt][2]);
            g_vT[vb + TT + tp + 8] = __float2half_rn(acc[2][mt][nt][3]);
        }
    }
}

// ===========================================================================
// Kernel 2: fp16 register-resident causal flash attention (R12, known good).
// ===========================================================================
#define KH_STRIDE 136
#define VT_STRIDE 72
#define ATTN_SMEM ((64 * KH_STRIDE + 128 * VT_STRIDE) * 2)   // 35840 B

__global__ __launch_bounds__(128, 2) void attn_fa2_kernel(float* __restrict__ out)
{
    extern __shared__ __half smh[];
    __half* Ksh = smh;                        // [64][136]
    __half* Vth = smh + 64 * KH_STRIDE;       // [128][72] V^T; also Q staging
    const uint32_t Ks_a = smem_u32(Ksh);
    const uint32_t Vt_a = smem_u32(Vth);
    const uint32_t* Ks32 = reinterpret_cast<const uint32_t*>(Ksh);
    const uint32_t* Vt32 = reinterpret_cast<const uint32_t*>(Vth);

    const int b  = blockIdx.y;
    const int qt = (int)gridDim.x - 1 - (int)blockIdx.x;
    const int q0 = qt * 64;
    const int tid  = threadIdx.x;
    const int wid  = tid >> 5;
    const int lane = tid & 31;
    const int g = lane >> 2;
    const int t = lane & 3;

    const int r0l = wid * 16 + g;
    const int r1l = r0l + 8;

    const __half* kbase  = g_kh + (size_t)b * TT * HH;
    const __half* vtbase = g_vT + (size_t)b * HH * TT;

    {
        #pragma unroll
        for (int p = 0; p < 8; p++) {
            int idx = tid + p * 128;
            int r = idx >> 4, ch = idx & 15;
            cp_async16(Ks_a + (uint32_t)(r * KH_STRIDE + ch * 8) * 2,
                       kbase + (size_t)r * HH + ch * 8);
        }
        cp_async_commit();
    }
    {
        const __half* qg = g_qh + ((size_t)b * TT + q0) * HH;
        #pragma unroll
        for (int p = 0; p < 8; p++) {
            int idx = tid + p * 128;
            int r = idx >> 4, ch = idx & 15;
            *reinterpret_cast<uint4*>(&Vth[r * KH_STRIDE + ch * 8]) =
                *reinterpret_cast<const uint4*>(&qg[(size_t)r * HH + ch * 8]);
        }
    }
    __syncthreads();

    uint32_t qfr[8][4];
    #pragma unroll
    for (int ks = 0; ks < 8; ks++) {
        qfr[ks][0] = Vt32[68 * r0l + 8 * ks + t];
        qfr[ks][1] = Vt32[68 * r1l + 8 * ks + t];
        qfr[ks][2] = Vt32[68 * r0l + 8 * ks + t + 4];
        qfr[ks][3] = Vt32[68 * r1l + 8 * ks + t + 4];
    }

    float m0 = -INFINITY, m1 = -INFINITY, l0 = 0.0f, l1 = 0.0f;
    float oacc[16][4];
    #pragma unroll
    for (int nt = 0; nt < 16; nt++)
        #pragma unroll
        for (int e = 0; e < 4; e++) oacc[nt][e] = 0.0f;

    const int nkt = qt + 1;
    for (int kt = 0; kt < nkt; kt++) {
        cp_async_wait_all();
        __syncthreads();

        {
            #pragma unroll
            for (int p = 0; p < 8; p++) {
                int idx = tid + p * 128;
                int h = idx >> 3, ch = idx & 7;
                cp_async16(Vt_a + (uint32_t)(h * VT_STRIDE + ch * 8) * 2,
                           vtbase + (size_t)h * TT + kt * 64 + ch * 8);
            }
            cp_async_commit();
        }

        float sacc[8][4];
        #pragma unroll
        for (int nt = 0; nt < 8; nt++)
            #pragma unroll
            for (int e = 0; e < 4; e++) sacc[nt][e] = 0.0f;

        #pragma unroll
        for (int ks = 0; ks < 8; ks++) {
            #pragma unroll
            for (int nt = 0; nt < 8; nt++) {
                const int n = nt * 8 + g;
                mma16(sacc[nt], qfr[ks],
                      Ks32[68 * n + 8 * ks + t],
                      Ks32[68 * n + 8 * ks + t + 4]);
            }
        }

        if (kt == qt) {
            #pragma unroll
            for (int nt = 0; nt < 8; nt++) {
                const int cl = nt * 8 + 2 * t;
                if (cl     > r0l) sacc[nt][0] = -INFINITY;
                if (cl + 1 > r0l) sacc[nt][1] = -INFINITY;
                if (cl     > r1l) sacc[nt][2] = -INFINITY;
                if (cl + 1 > r1l) sacc[nt][3] = -INFINITY;
            }
        }

        float mx0 = -INFINITY, mx1 = -INFINITY;
        #pragma unroll
        for (int nt = 0; nt < 8; nt++) {
            mx0 = fmaxf(mx0, fmaxf(sacc[nt][0], sacc[nt][1]));
            mx1 = fmaxf(mx1, fmaxf(sacc[nt][2], sacc[nt][3]));
        }
        mx0 = fmaxf(mx0, __shfl_xor_sync(0xffffffffu, mx0, 1));
        mx0 = fmaxf(mx0, __shfl_xor_sync(0xffffffffu, mx0, 2));
        mx1 = fmaxf(mx1, __shfl_xor_sync(0xffffffffu, mx1, 1));
        mx1 = fmaxf(mx1, __shfl_xor_sync(0xffffffffu, mx1, 2));

        const float m0n = fmaxf(m0, mx0);
        const float m1n = fmaxf(m1, mx1);
        const float c0 = __expf(m0 - m0n);
        const float c1 = __expf(m1 - m1n);

        float s0 = 0.0f, s1 = 0.0f;
        #pragma unroll
        for (int nt = 0; nt < 8; nt++) {
            sacc[nt][0] = __expf(sacc[nt][0] - m0n);
            sacc[nt][1] = __expf(sacc[nt][1] - m0n);
            sacc[nt][2] = __expf(sacc[nt][2] - m1n);
            sacc[nt][3] = __expf(sacc[nt][3] - m1n);
            s0 += sacc[nt][0] + sacc[nt][1];
            s1 += sacc[nt][2] + sacc[nt][3];
        }
        s0 += __shfl_xor_sync(0xffffffffu, s0, 1);
        s0 += __shfl_xor_sync(0xffffffffu, s0, 2);
        s1 += __shfl_xor_sync(0xffffffffu, s1, 1);
        s1 += __shfl_xor_sync(0xffffffffu, s1, 2);

        l0 = l0 * c0 + s0;
        l1 = l1 * c1 + s1;
        m0 = m0n;
        m1 = m1n;

        #pragma unroll
        for (int nt = 0; nt < 16; nt++) {
            oacc[nt][0] *= c0; oacc[nt][1] *= c0;
            oacc[nt][2] *= c1; oacc[nt][3] *= c1;
        }

        cp_async_wait_all();
        __syncthreads();

        if (kt + 1 < nkt) {
            const __half* kg = kbase + (size_t)(kt + 1) * 64 * HH;
            #pragma unroll
            for (int p = 0; p < 8; p++) {
                int idx = tid + p * 128;
                int r = idx >> 4, ch = idx & 15;
                cp_async16(Ks_a + (uint32_t)(r * KH_STRIDE + ch * 8) * 2,
                           kg + (size_t)r * HH + ch * 8);
            }
            cp_async_commit();
        }

        #pragma unroll
        for (int kk = 0; kk < 4; kk++) {
            uint32_t afr[4];
            afr[0] = packh2(sacc[2 * kk][0],     sacc[2 * kk][1]);
            afr[1] = packh2(sacc[2 * kk][2],     sacc[2 * kk][3]);
            afr[2] = packh2(sacc[2 * kk + 1][0], sacc[2 * kk + 1][1]);
            afr[3] = packh2(sacc[2 * kk + 1][2], sacc[2 * kk + 1][3]);
            #pragma unroll
            for (int nt = 0; nt < 16; nt++) {
                const int n = nt * 8 + g;
                mma16(oacc[nt], afr,
                      Vt32[36 * n + 8 * kk + t],
                      Vt32[36 * n + 8 * kk + t + 4]);
            }
        }
    }

    const float inv0 = 1.0f / l0;
    const float inv1 = 1.0f / l1;
    float* og = out + ((size_t)b * TT + q0) * HH;
    #pragma unroll
    for (int nt = 0; nt < 16; nt++) {
        const int col = nt * 8 + 2 * t;
        *reinterpret_cast<float2*>(&og[(size_t)r0l * HH + col]) =
            make_float2(oacc[nt][0] * inv0, oacc[nt][1] * inv0);
        *reinterpret_cast<float2*>(&og[(size_t)r1l * HH + col]) =
            make_float2(oacc[nt][2] * inv1, oacc[nt][3] * inv1);
    }
}

// ===========================================================================
// Launch
// ===========================================================================
extern "C" void kernel_launch(void* const* d_in, const int* in_sizes, int n_in,
                              void* d_out, int out_size)
{
    const float* x  = (const float*)d_in[0];
    const float* Wq = (const float*)d_in[1];
    const float* Wk = (const float*)d_in[2];
    const float* Wv = (const float*)d_in[3];
    float* out = (float*)d_out;

    cudaFuncSetAttribute(qkv_fused_kernel,
                         cudaFuncAttributeMaxDynamicSharedMemorySize, QKV_SMEM);
    cudaFuncSetAttribute(attn_fa2_kernel,
                         cudaFuncAttributeMaxDynamicSharedMemorySize, ATTN_SMEM);

    conv_w_kernel<<<96, 256>>>(Wq, Wk, Wv);
    qkv_fused_kernel<<<TT * BB / 128, 256, QKV_SMEM>>>(x);
    attn_fa2_kernel<<<dim3(TT / 64, BB), 128, ATTN_SMEM>>>(out);
}

// round 14
// speedup vs baseline: 1.6633x; 1.0197x over previous
#include <cuda_runtime.h>
#include <cuda_fp16.h>
#include <cstdint>
#include <math.h>

#define BB 16
#define TT 2048
#define CC 768
#define HH 128

// g_wh: W^T fp16, per weight [n=128][k=768], k permuted in 32-half chunks
// (pos16 word permutation), Wq pre-scaled.
__device__ __half g_wh[3 * CC * HH];
// Attention inputs, fp16:
//   g_qh, g_kh: [b][t][h] row-major (Q pre-scaled)
//   g_vT:       [b][h][t] transposed
__device__ __half g_qh[BB * TT * HH];
__device__ __half g_kh[BB * TT * HH];
__device__ __half g_vT[BB * HH * TT];

// ---------------------------------------------------------------------------
// helpers
// ---------------------------------------------------------------------------
__device__ __forceinline__ uint32_t packh2(float lo, float hi) {
    uint32_t d;
    asm("cvt.rn.f16x2.f32 %0, %1, %2;" : "=r"(d) : "f"(hi), "f"(lo));
    return d;
}

__device__ __forceinline__ void mma16(float* d, const uint32_t* a,
                                      uint32_t b0, uint32_t b1) {
    asm volatile(
        "mma.sync.aligned.m16n8k16.row.col.f32.f16.f16.f32 "
        "{%0,%1,%2,%3}, {%4,%5,%6,%7}, {%8,%9}, {%0,%1,%2,%3};"
        : "+f"(d[0]), "+f"(d[1]), "+f"(d[2]), "+f"(d[3])
        : "r"(a[0]), "r"(a[1]), "r"(a[2]), "r"(a[3]),
          "r"(b0), "r"(b1));
}

__device__ __forceinline__ void cp_async16(uint32_t smem_dst, const void* gmem_src) {
    asm volatile("cp.async.cg.shared.global [%0], [%1], 16;"
                 :: "r"(smem_dst), "l"(gmem_src) : "memory");
}
__device__ __forceinline__ void cp_async_commit() {
    asm volatile("cp.async.commit_group;" ::: "memory");
}
__device__ __forceinline__ void cp_async_wait_all() {
    asm volatile("cp.async.wait_group 0;" ::: "memory");
}
__device__ __forceinline__ void cp_async_wait_1() {
    asm volatile("cp.async.wait_group 1;" ::: "memory");
}

__device__ __forceinline__ uint32_t smem_u32(const void* p) {
    uint32_t a;
    asm("{ .reg .u64 t; cvta.to.shared.u64 t, %1; cvt.u32.u64 %0, t; }"
        : "=r"(a) : "l"(p));
    return a;
}

__device__ __forceinline__ int pos16(int w) {
    return (w & 3) * 4 + ((w >> 3) & 1) * 2 + ((w >> 2) & 1);
}

// ===========================================================================
// Kernel 0: build g_wh = W^T fp16 with permuted k (Wq pre-scaled, rn).
// One element per thread, big grid (latency-bound otherwise).
// ===========================================================================
__global__ __launch_bounds__(256) void conv_w_kernel(
    const float* __restrict__ Wq,
    const float* __restrict__ Wk,
    const float* __restrict__ Wv)
{
    const int per = CC * HH;
    const int i = blockIdx.x * blockDim.x + threadIdx.x;
    if (i >= 3 * per) return;
    const float* Ws[3] = {Wq, Wk, Wv};
    int w = i / per, rem = i - w * per;
    int n = rem / CC, k = rem - n * CC;
    float s = (w == 0) ? 0.03608439182435161f : 1.0f;
    float v = Ws[w][(size_t)k * HH + n] * s;
    int chunk = k >> 5, kl = k & 31;
    int word = kl >> 1, h = kl & 1;
    int pos = chunk * 32 + pos16(word) * 2 + h;
    g_wh[((size_t)w * HH + n) * CC + pos] = __float2half_rn(v);
}

// ===========================================================================
// Kernel 1: fused QKV projection, fp16 m16n8k16 mainloop, 2-stage cp.async
// (unchanged from R13 — known good).
// ===========================================================================
#define NCH 24

#define AS_STRIDE 36
#define BROW_WORDS 20
#define A_BUF (128 * AS_STRIDE)
#define B_ALL (3 * 128 * BROW_WORDS)
#define STAGE_WORDS (A_BUF + B_ALL)
#define QKV_SMEM (2 * STAGE_WORDS * 4)

__global__ __launch_bounds__(256) void qkv_fused_kernel(const float* __restrict__ x)
{
    extern __shared__ uint32_t sm_u[];
    const uint32_t sm_a = smem_u32(sm_u);

    const int tid  = threadIdx.x;
    const int lane = tid & 31;
    const int wid  = tid >> 5;
    const int g = lane >> 2;
    const int t = lane & 3;
    const int wr = wid & 3;
    const int wc = wid >> 2;
    const int m0 = blockIdx.x * 128;

    float acc[3][2][8][4];
    #pragma unroll
    for (int w = 0; w < 3; w++)
        #pragma unroll
        for (int mt = 0; mt < 2; mt++)
            #pragma unroll
            for (int nt = 0; nt < 8; nt++)
                #pragma unroll
                for (int e = 0; e < 4; e++) acc[w][mt][nt][e] = 0.0f;

    auto issue_stage = [&](int c, int buf) {
        const uint32_t base = sm_a + (uint32_t)buf * STAGE_WORDS * 4;
        const float* xg = x + (size_t)m0 * CC + c * 32;
        #pragma unroll
        for (int p = 0; p < 4; p++) {
            int idx = tid + p * 256;
            int m = idx >> 3, k4 = (idx & 7) << 2;
            cp_async16(base + (uint32_t)(m * AS_STRIDE + k4) * 4,
                       xg + (size_t)m * CC + k4);
        }
        #pragma unroll
        for (int p = 0; p < 6; p++) {
            int idx = tid + p * 256;
            int n_all = idx >> 2;
            int ch = idx & 3;
            cp_async16(base + (uint32_t)(A_BUF + n_all * BROW_WORDS + ch * 4) * 4,
                       g_wh + (size_t)n_all * CC + c * 32 + ch * 8);
        }
        cp_async_commit();
    };

    issue_stage(0, 0);

    for (int c = 0; c < NCH; c++) {
        const int buf = c & 1;
        __syncthreads();
        if (c + 1 < NCH) {
            issue_stage(c + 1, buf ^ 1);
            cp_async_wait_1();
        } else {
            cp_async_wait_all();
        }
        __syncthreads();

        const uint32_t* As = sm_u + buf * STAGE_WORDS;
        const uint32_t* Bs = As + A_BUF;
        const float2* A2 = reinterpret_cast<const float2*>(As);

        uint32_t afr[2][2][4];
        #pragma unroll
        for (int ks = 0; ks < 2; ks++) {
            #pragma unroll
            for (int mt = 0; mt < 2; mt++) {
                const int rb = wr * 32 + mt * 16;
                float2 p0 = A2[(rb + g)     * 18 + ks * 8 + t];
                float2 p1 = A2[(rb + g + 8) * 18 + ks * 8 + t];
                float2 p2 = A2[(rb + g)     * 18 + ks * 8 + t + 4];
                float2 p3 = A2[(rb + g + 8) * 18 + ks * 8 + t + 4];
                afr[ks][mt][0] = packh2(p0.x, p0.y);
                afr[ks][mt][1] = packh2(p1.x, p1.y);
                afr[ks][mt][2] = packh2(p2.x, p2.y);
                afr[ks][mt][3] = packh2(p3.x, p3.y);
            }
        }

        #pragma unroll
        for (int w = 0; w < 3; w++) {
            #pragma unroll
            for (int nt = 0; nt < 8; nt++) {
                const int n_all = w * 128 + wc * 64 + nt * 8 + g;
                uint4 bq = *reinterpret_cast<const uint4*>(
                    &Bs[n_all * BROW_WORDS + t * 4]);
                mma16(acc[w][0][nt], afr[0][0], bq.x, bq.y);
                mma16(acc[w][1][nt], afr[0][1], bq.x, bq.y);
                mma16(acc[w][0][nt], afr[1][0], bq.z, bq.w);
                mma16(acc[w][1][nt], afr[1][1], bq.z, bq.w);
            }
        }
    }

    __half* outs2[2] = {g_qh, g_kh};
    #pragma unroll
    for (int mt = 0; mt < 2; mt++) {
        const int r0 = m0 + wr * 32 + mt * 16 + g;
        const int bq = r0 >> 11;
        const int tp = r0 & 2047;
        #pragma unroll
        for (int nt = 0; nt < 8; nt++) {
            const int col = wc * 64 + nt * 8 + 2 * t;
            #pragma unroll
            for (int w = 0; w < 2; w++) {
                __half* outw = outs2[w];
                *reinterpret_cast<uint32_t*>(&outw[(size_t)r0 * HH + col]) =
                    packh2(acc[w][mt][nt][0], acc[w][mt][nt][1]);
                *reinterpret_cast<uint32_t*>(&outw[(size_t)(r0 + 8) * HH + col]) =
                    packh2(acc[w][mt][nt][2], acc[w][mt][nt][3]);
            }
            const size_t vb = ((size_t)bq * HH + col) * TT;
            g_vT[vb + tp]          = __float2half_rn(acc[2][mt][nt][0]);
            g_vT[vb + TT + tp]     = __float2half_rn(acc[2][mt][nt][1]);
            g_vT[vb + tp + 8]      = __float2half_rn(acc[2][mt][nt][2]);
            g_vT[vb + TT + tp + 8] = __float2half_rn(acc[2][mt][nt][3]);
        }
    }
}

// ===========================================================================
// Kernel 2: fp16 causal flash attention, DOUBLE-buffered {K,V} stages.
// Stage s = {K[s], V^T[s]} committed as one cp.async group, issued two
// iterations ahead. One wait + two syncs per tile. Q frags via direct LDG.
// ===========================================================================
#define KH_STRIDE 136   // halfs per K row
#define VT_STRIDE 72    // halfs per V^T row
#define K_ST_H (64 * KH_STRIDE)     // halfs per K stage
#define V_ST_H (128 * VT_STRIDE)    // halfs per V stage
#define ATTN_SMEM ((2 * K_ST_H + 2 * V_ST_H) * 2)   // 71680 B

__global__ __launch_bounds__(128, 2) void attn_fa2_kernel(float* __restrict__ out)
{
    extern __shared__ __half smh[];
    __half* Ksh = smh;                    // [2][64][136]
    __half* Vth = smh + 2 * K_ST_H;       // [2][128][72]
    const uint32_t Ks_a = smem_u32(Ksh);
    const uint32_t Vt_a = smem_u32(Vth);

    const int b  = blockIdx.y;
    const int qt = (int)gridDim.x - 1 - (int)blockIdx.x;   // heavy tiles first
    const int q0 = qt * 64;
    const int tid  = threadIdx.x;
    const int wid  = tid >> 5;
    const int lane = tid & 31;
    const int g = lane >> 2;
    const int t = lane & 3;

    const int r0l = wid * 16 + g;
    const int r1l = r0l + 8;

    const __half* kbase  = g_kh + (size_t)b * TT * HH;
    const __half* vtbase = g_vT + (size_t)b * HH * TT;
    const int nkt = qt + 1;

    // issue one {K,V} stage (16 cp.async/thread + 1 commit)
    auto issue_stage = [&](int s) {
        const int buf = s & 1;
        const __half* kg = kbase + (size_t)s * 64 * HH;
        #pragma unroll
        for (int p = 0; p < 8; p++) {
            int idx = tid + p * 128;
            int r = idx >> 4, ch = idx & 15;
            cp_async16(Ks_a + (uint32_t)(buf * K_ST_H + r * KH_STRIDE + ch * 8) * 2,
                       kg + (size_t)r * HH + ch * 8);
        }
        #pragma unroll
        for (int p = 0; p < 8; p++) {
            int idx = tid + p * 128;
            int h = idx >> 3, ch = idx & 7;
            cp_async16(Vt_a + (uint32_t)(buf * V_ST_H + h * VT_STRIDE + ch * 8) * 2,
                       vtbase + (size_t)h * TT + s * 64 + ch * 8);
        }
        cp_async_commit();
    };

    // prologue: two stages in flight
    issue_stage(0);
    if (nkt > 1) issue_stage(1);

    // Q fragments via direct global loads (coalesced uint32, L2-resident)
    uint32_t qfr[8][4];
    {
        const uint32_t* qg0 = reinterpret_cast<const uint32_t*>(
            g_qh + ((size_t)b * TT + q0 + r0l) * HH);
        const uint32_t* qg1 = reinterpret_cast<const uint32_t*>(
            g_qh + ((size_t)b * TT + q0 + r1l) * HH);
        #pragma unroll
        for (int ks = 0; ks < 8; ks++) {
            qfr[ks][0] = qg0[8 * ks + t];
            qfr[ks][1] = qg1[8 * ks + t];
            qfr[ks][2] = qg0[8 * ks + t + 4];
            qfr[ks][3] = qg1[8 * ks + t + 4];
        }
    }

    float m0 = -INFINITY, m1 = -INFINITY, l0 = 0.0f, l1 = 0.0f;
    float oacc[16][4];
    #pragma unroll
    for (int nt = 0; nt < 16; nt++)
        #pragma unroll
        for (int e = 0; e < 4; e++) oacc[nt][e] = 0.0f;

    for (int kt = 0; kt < nkt; kt++) {
        const int buf = kt & 1;
        const uint32_t* Ks32 = reinterpret_cast<const uint32_t*>(Ksh + buf * K_ST_H);
        const uint32_t* Vt32 = reinterpret_cast<const uint32_t*>(Vth + buf * V_ST_H);

        // stage kt complete (stage kt+1 may still be in flight)
        if (kt + 1 < nkt) cp_async_wait_1(); else cp_async_wait_all();
        __syncthreads();

        // ---- S = Q K^T ----
        float sacc[8][4];
        #pragma unroll
        for (int nt = 0; nt < 8; nt++)
            #pragma unroll
            for (int e = 0; e < 4; e++) sacc[nt][e] = 0.0f;

        #pragma unroll
        for (int ks = 0; ks < 8; ks++) {
            #pragma unroll
            for (int nt = 0; nt < 8; nt++) {
                const int n = nt * 8 + g;
                mma16(sacc[nt], qfr[ks],
                      Ks32[68 * n + 8 * ks + t],
                      Ks32[68 * n + 8 * ks + t + 4]);
            }
        }

        if (kt == qt) {
            #pragma unroll
            for (int nt = 0; nt < 8; nt++) {
                const int cl = nt * 8 + 2 * t;
                if (cl     > r0l) sacc[nt][0] = -INFINITY;
                if (cl + 1 > r0l) sacc[nt][1] = -INFINITY;
                if (cl     > r1l) sacc[nt][2] = -INFINITY;
                if (cl + 1 > r1l) sacc[nt][3] = -INFINITY;
            }
        }

        // ---- online softmax ----
        float mx0 = -INFINITY, mx1 = -INFINITY;
        #pragma unroll
        for (int nt = 0; nt < 8; nt++) {
            mx0 = fmaxf(mx0, fmaxf(sacc[nt][0], sacc[nt][1]));
            mx1 = fmaxf(mx1, fmaxf(sacc[nt][2], sacc[nt][3]));
        }
        mx0 = fmaxf(mx0, __shfl_xor_sync(0xffffffffu, mx0, 1));
        mx0 = fmaxf(mx0, __shfl_xor_sync(0xffffffffu, mx0, 2));
        mx1 = fmaxf(mx1, __shfl_xor_sync(0xffffffffu, mx1, 1));
        mx1 = fmaxf(mx1, __shfl_xor_sync(0xffffffffu, mx1, 2));

        const float m0n = fmaxf(m0, mx0);
        const float m1n = fmaxf(m1, mx1);
        const float c0 = __expf(m0 - m0n);
        const float c1 = __expf(m1 - m1n);

        float s0 = 0.0f, s1 = 0.0f;
        #pragma unroll
        for (int nt = 0; nt < 8; nt++) {
            sacc[nt][0] = __expf(sacc[nt][0] - m0n);
            sacc[nt][1] = __expf(sacc[nt][1] - m0n);
            sacc[nt][2] = __expf(sacc[nt][2] - m1n);
            sacc[nt][3] = __expf(sacc[nt][3] - m1n);
            s0 += sacc[nt][0] + sacc[nt][1];
            s1 += sacc[nt][2] + sacc[nt][3];
        }
        s0 += __shfl_xor_sync(0xffffffffu, s0, 1);
        s0 += __shfl_xor_sync(0xffffffffu, s0, 2);
        s1 += __shfl_xor_sync(0xffffffffu, s1, 1);
        s1 += __shfl_xor_sync(0xffffffffu, s1, 2);

        l0 = l0 * c0 + s0;
        l1 = l1 * c1 + s1;
        m0 = m0n;
        m1 = m1n;

        #pragma unroll
        for (int nt = 0; nt < 16; nt++) {
            oacc[nt][0] *= c0; oacc[nt][1] *= c0;
            oacc[nt][2] *= c1; oacc[nt][3] *= c1;
        }

        // ---- O += P V (P packs directly into A-frags, no shuffles) ----
        #pragma unroll
        for (int kk = 0; kk < 4; kk++) {
            uint32_t afr[4];
            afr[0] = packh2(sacc[2 * kk][0],     sacc[2 * kk][1]);
            afr[1] = packh2(sacc[2 * kk][2],     sacc[2 * kk][3]);
            afr[2] = packh2(sacc[2 * kk + 1][0], sacc[2 * kk + 1][1]);
            afr[3] = packh2(sacc[2 * kk + 1][2], sacc[2 * kk + 1][3]);
            #pragma unroll
            for (int nt = 0; nt < 16; nt++) {
                const int n = nt * 8 + g;
                mma16(oacc[nt], afr,
                      Vt32[36 * n + 8 * kk + t],
                      Vt32[36 * n + 8 * kk + t + 4]);
            }
        }

        // all warps done with stage kt -> refill its buffer with stage kt+2
        if (kt + 2 < nkt) {
            __syncthreads();
            issue_stage(kt + 2);
        }
    }

    // ---- epilogue ----
    const float inv0 = 1.0f / l0;
    const float inv1 = 1.0f / l1;
    float* og = out + ((size_t)b * TT + q0) * HH;
    #pragma unroll
    for (int nt = 0; nt < 16; nt++) {
        const int col = nt * 8 + 2 * t;
        *reinterpret_cast<float2*>(&og[(size_t)r0l * HH + col]) =
            make_float2(oacc[nt][0] * inv0, oacc[nt][1] * inv0);
        *reinterpret_cast<float2*>(&og[(size_t)r1l * HH + col]) =
            make_float2(oacc[nt][2] * inv1, oacc[nt][3] * inv1);
    }
}

// ===========================================================================
// Launch
// ===========================================================================
extern "C" void kernel_launch(void* const* d_in, const int* in_sizes, int n_in,
                              void* d_out, int out_size)
{
    const float* x  = (const float*)d_in[0];
    const float* Wq = (const float*)d_in[1];
    const float* Wk = (const float*)d_in[2];
    const float* Wv = (const float*)d_in[3];
    float* out = (float*)d_out;

    cudaFuncSetAttribute(qkv_fused_kernel,
                         cudaFuncAttributeMaxDynamicSharedMemorySize, QKV_SMEM);
    cudaFuncSetAttribute(attn_fa2_kernel,
                         cudaFuncAttributeMaxDynamicSharedMemorySize, ATTN_SMEM);

    conv_w_kernel<<<(3 * CC * HH + 255) / 256, 256>>>(Wq, Wk, Wv);
    qkv_fused_kernel<<<TT * BB / 128, 256, QKV_SMEM>>>(x);
    attn_fa2_kernel<<<dim3(TT / 64, BB), 128, ATTN_SMEM>>>(out);
}

// round 15
// speedup vs baseline: 1.8458x; 1.1097x over previous
#include <cuda_runtime.h>
#include <cuda_fp16.h>
#include <cstdint>
#include <math.h>

#define BB 16
#define TT 2048
#define CC 768
#define HH 128

// g_wh: W^T fp16, per weight [n=128][k=768], k permuted in 32-half chunks
// (pos16 word permutation), Wq pre-scaled.
__device__ __half g_wh[3 * CC * HH];
// Attention inputs, fp16:
//   g_qh, g_kh: [b][t][h] row-major (Q pre-scaled)
//   g_vT:       [b][h][t] transposed
__device__ __half g_qh[BB * TT * HH];
__device__ __half g_kh[BB * TT * HH];
__device__ __half g_vT[BB * HH * TT];

// ---------------------------------------------------------------------------
// helpers
// ---------------------------------------------------------------------------
__device__ __forceinline__ uint32_t packh2(float lo, float hi) {
    uint32_t d;
    asm("cvt.rn.f16x2.f32 %0, %1, %2;" : "=r"(d) : "f"(hi), "f"(lo));
    return d;
}

__device__ __forceinline__ void mma16(float* d, const uint32_t* a,
                                      uint32_t b0, uint32_t b1) {
    asm volatile(
        "mma.sync.aligned.m16n8k16.row.col.f32.f16.f16.f32 "
        "{%0,%1,%2,%3}, {%4,%5,%6,%7}, {%8,%9}, {%0,%1,%2,%3};"
        : "+f"(d[0]), "+f"(d[1]), "+f"(d[2]), "+f"(d[3])
        : "r"(a[0]), "r"(a[1]), "r"(a[2]), "r"(a[3]),
          "r"(b0), "r"(b1));
}

__device__ __forceinline__ void cp_async16(uint32_t smem_dst, const void* gmem_src) {
    asm volatile("cp.async.cg.shared.global [%0], [%1], 16;"
                 :: "r"(smem_dst), "l"(gmem_src) : "memory");
}
__device__ __forceinline__ void cp_async_commit() {
    asm volatile("cp.async.commit_group;" ::: "memory");
}
__device__ __forceinline__ void cp_async_wait_all() {
    asm volatile("cp.async.wait_group 0;" ::: "memory");
}
__device__ __forceinline__ void cp_async_wait_1() {
    asm volatile("cp.async.wait_group 1;" ::: "memory");
}

__device__ __forceinline__ uint32_t smem_u32(const void* p) {
    uint32_t a;
    asm("{ .reg .u64 t; cvta.to.shared.u64 t, %1; cvt.u32.u64 %0, t; }"
        : "=r"(a) : "l"(p));
    return a;
}

__device__ __forceinline__ int pos16(int w) {
    return (w & 3) * 4 + ((w >> 3) & 1) * 2 + ((w >> 2) & 1);
}

// ===========================================================================
// Kernel 0: build g_wh = W^T fp16 with permuted k (Wq pre-scaled, rn).
// CTA = one (32-k x 128-n) tile of one weight. Coalesced reads over n,
// smem transpose, 64B-contiguous permuted writes per n-row.
// ===========================================================================
__global__ __launch_bounds__(256) void conv_w_kernel(
    const float* __restrict__ Wq,
    const float* __restrict__ Wk,
    const float* __restrict__ Wv)
{
    __shared__ unsigned short sm_t[32 * 130];   // [kk][n], stride 130

    const int chunk = blockIdx.x;        // 0..23
    const int w     = blockIdx.y;        // 0..2
    const int k0    = chunk * 32;
    const int tid   = threadIdx.x;
    const float* W  = (w == 0) ? Wq : (w == 1) ? Wk : Wv;
    const float s   = (w == 0) ? 0.03608439182435161f : 1.0f;

    // load 32 x 128 coalesced (n fastest), convert, transpose into smem
    #pragma unroll
    for (int p = 0; p < 16; p++) {
        int idx = tid + p * 256;         // 0..4095
        int kk = idx >> 7, n = idx & 127;
        float v = W[(size_t)(k0 + kk) * HH + n] * s;
        __half hv = __float2half_rn(v);
        sm_t[kk * 130 + n] = *reinterpret_cast<unsigned short*>(&hv);
    }
    __syncthreads();

    // each of 128 threads emits one n-row's permuted 32-half chunk (64B)
    if (tid < 128) {
        const int n = tid;
        uint32_t row[16];
        #pragma unroll
        for (int word = 0; word < 16; word++) {
            uint32_t lo = sm_t[(2 * word)     * 130 + n];
            uint32_t hi = sm_t[(2 * word + 1) * 130 + n];
            row[pos16(word)] = lo | (hi << 16);
        }
        uint4* dst = reinterpret_cast<uint4*>(
            g_wh + ((size_t)w * HH + n) * CC + chunk * 32);
        dst[0] = make_uint4(row[0],  row[1],  row[2],  row[3]);
        dst[1] = make_uint4(row[4],  row[5],  row[6],  row[7]);
        dst[2] = make_uint4(row[8],  row[9],  row[10], row[11]);
        dst[3] = make_uint4(row[12], row[13], row[14], row[15]);
    }
}

// ===========================================================================
// Kernel 1: fused QKV projection, fp16 m16n8k16 mainloop, 2-stage cp.async.
// V epilogue now goes through a transposed smem tile -> coalesced g_vT writes.
// ===========================================================================
#define NCH 24

#define AS_STRIDE 36
#define BROW_WORDS 20
#define A_BUF (128 * AS_STRIDE)
#define B_ALL (3 * 128 * BROW_WORDS)
#define STAGE_WORDS (A_BUF + B_ALL)
#define QKV_SMEM (2 * STAGE_WORDS * 4)

__global__ __launch_bounds__(256) void qkv_fused_kernel(const float* __restrict__ x)
{
    extern __shared__ uint32_t sm_u[];
    const uint32_t sm_a = smem_u32(sm_u);

    const int tid  = threadIdx.x;
    const int lane = tid & 31;
    const int wid  = tid >> 5;
    const int g = lane >> 2;
    const int t = lane & 3;
    const int wr = wid & 3;
    const int wc = wid >> 2;
    const int m0 = blockIdx.x * 128;

    float acc[3][2][8][4];
    #pragma unroll
    for (int w = 0; w < 3; w++)
        #pragma unroll
        for (int mt = 0; mt < 2; mt++)
            #pragma unroll
            for (int nt = 0; nt < 8; nt++)
                #pragma unroll
                for (int e = 0; e < 4; e++) acc[w][mt][nt][e] = 0.0f;

    auto issue_stage = [&](int c, int buf) {
        const uint32_t base = sm_a + (uint32_t)buf * STAGE_WORDS * 4;
        const float* xg = x + (size_t)m0 * CC + c * 32;
        #pragma unroll
        for (int p = 0; p < 4; p++) {
            int idx = tid + p * 256;
            int m = idx >> 3, k4 = (idx & 7) << 2;
            cp_async16(base + (uint32_t)(m * AS_STRIDE + k4) * 4,
                       xg + (size_t)m * CC + k4);
        }
        #pragma unroll
        for (int p = 0; p < 6; p++) {
            int idx = tid + p * 256;
            int n_all = idx >> 2;
            int ch = idx & 3;
            cp_async16(base + (uint32_t)(A_BUF + n_all * BROW_WORDS + ch * 4) * 4,
                       g_wh + (size_t)n_all * CC + c * 32 + ch * 8);
        }
        cp_async_commit();
    };

    issue_stage(0, 0);

    for (int c = 0; c < NCH; c++) {
        const int buf = c & 1;
        __syncthreads();
        if (c + 1 < NCH) {
            issue_stage(c + 1, buf ^ 1);
            cp_async_wait_1();
        } else {
            cp_async_wait_all();
        }
        __syncthreads();

        const uint32_t* As = sm_u + buf * STAGE_WORDS;
        const uint32_t* Bs = As + A_BUF;
        const float2* A2 = reinterpret_cast<const float2*>(As);

        uint32_t afr[2][2][4];
        #pragma unroll
        for (int ks = 0; ks < 2; ks++) {
            #pragma unroll
            for (int mt = 0; mt < 2; mt++) {
                const int rb = wr * 32 + mt * 16;
                float2 p0 = A2[(rb + g)     * 18 + ks * 8 + t];
                float2 p1 = A2[(rb + g + 8) * 18 + ks * 8 + t];
                float2 p2 = A2[(rb + g)     * 18 + ks * 8 + t + 4];
                float2 p3 = A2[(rb + g + 8) * 18 + ks * 8 + t + 4];
                afr[ks][mt][0] = packh2(p0.x, p0.y);
                afr[ks][mt][1] = packh2(p1.x, p1.y);
                afr[ks][mt][2] = packh2(p2.x, p2.y);
                afr[ks][mt][3] = packh2(p3.x, p3.y);
            }
        }

        #pragma unroll
        for (int w = 0; w < 3; w++) {
            #pragma unroll
            for (int nt = 0; nt < 8; nt++) {
                const int n_all = w * 128 + wc * 64 + nt * 8 + g;
                uint4 bq = *reinterpret_cast<const uint4*>(
                    &Bs[n_all * BROW_WORDS + t * 4]);
                mma16(acc[w][0][nt], afr[0][0], bq.x, bq.y);
                mma16(acc[w][1][nt], afr[0][1], bq.x, bq.y);
                mma16(acc[w][0][nt], afr[1][0], bq.z, bq.w);
                mma16(acc[w][1][nt], afr[1][1], bq.z, bq.w);
            }
        }
    }

    // ---- epilogue part 1: Q/K row-major half2 (coalesced) ----
    __half* outs2[2] = {g_qh, g_kh};
    #pragma unroll
    for (int mt = 0; mt < 2; mt++) {
        const int r0 = m0 + wr * 32 + mt * 16 + g;
        #pragma unroll
        for (int nt = 0; nt < 8; nt++) {
            const int col = wc * 64 + nt * 8 + 2 * t;
            #pragma unroll
            for (int w = 0; w < 2; w++) {
                __half* outw = outs2[w];
                *reinterpret_cast<uint32_t*>(&outw[(size_t)r0 * HH + col]) =
                    packh2(acc[w][mt][nt][0], acc[w][mt][nt][1]);
                *reinterpret_cast<uint32_t*>(&outw[(size_t)(r0 + 8) * HH + col]) =
                    packh2(acc[w][mt][nt][2], acc[w][mt][nt][3]);
            }
        }
    }

    // ---- epilogue part 2: V transposed through smem, coalesced writes ----
    __syncthreads();   // done with stage buffers
    __half* vt_sm = reinterpret_cast<__half*>(sm_u);    // [128 cols][136]
    #pragma unroll
    for (int mt = 0; mt < 2; mt++) {
        const int r = wr * 32 + mt * 16 + g;            // local row
        #pragma unroll
        for (int nt = 0; nt < 8; nt++) {
            const int col = wc * 64 + nt * 8 + 2 * t;
            vt_sm[col * 136 + r]           = __float2half_rn(acc[2][mt][nt][0]);
            vt_sm[(col + 1) * 136 + r]     = __float2half_rn(acc[2][mt][nt][1]);
            vt_sm[col * 136 + r + 8]       = __float2half_rn(acc[2][mt][nt][2]);
            vt_sm[(col + 1) * 136 + r + 8] = __float2half_rn(acc[2][mt][nt][3]);
        }
    }
    __syncthreads();
    {
        const int bq = m0 >> 11;            // batch
        const int tp0 = m0 & 2047;          // token offset within batch
        // 128 h-rows x 128 halfs = 2048 16B chunks; 8 per thread, coalesced
        #pragma unroll
        for (int p = 0; p < 8; p++) {
            int idx = tid + p * 256;
            int h = idx >> 4, ch = idx & 15;
            *reinterpret_cast<uint4*>(
                &g_vT[((size_t)bq * HH + h) * TT + tp0 + ch * 8]) =
                *reinterpret_cast<const uint4*>(&vt_sm[h * 136 + ch * 8]);
        }
    }
}

// ===========================================================================
// Kernel 2: fp16 causal flash attention, double-buffered {K,V} stages
// (unchanged from R14 — known good).
// ===========================================================================
#define KH_STRIDE 136
#define VT_STRIDE 72
#define K_ST_H (64 * KH_STRIDE)
#define V_ST_H (128 * VT_STRIDE)
#define ATTN_SMEM ((2 * K_ST_H + 2 * V_ST_H) * 2)   // 71680 B

__global__ __launch_bounds__(128, 2) void attn_fa2_kernel(float* __restrict__ out)
{
    extern __shared__ __half smh[];
    __half* Ksh = smh;                    // [2][64][136]
    __half* Vth = smh + 2 * K_ST_H;       // [2][128][72]
    const uint32_t Ks_a = smem_u32(Ksh);
    const uint32_t Vt_a = smem_u32(Vth);

    const int b  = blockIdx.y;
    const int qt = (int)gridDim.x - 1 - (int)blockIdx.x;
    const int q0 = qt * 64;
    const int tid  = threadIdx.x;
    const int wid  = tid >> 5;
    const int lane = tid & 31;
    const int g = lane >> 2;
    const int t = lane & 3;

    const int r0l = wid * 16 + g;
    const int r1l = r0l + 8;

    const __half* kbase  = g_kh + (size_t)b * TT * HH;
    const __half* vtbase = g_vT + (size_t)b * HH * TT;
    const int nkt = qt + 1;

    auto issue_stage = [&](int s) {
        const int buf = s & 1;
        const __half* kg = kbase + (size_t)s * 64 * HH;
        #pragma unroll
        for (int p = 0; p < 8; p++) {
            int idx = tid + p * 128;
            int r = idx >> 4, ch = idx & 15;
            cp_async16(Ks_a + (uint32_t)(buf * K_ST_H + r * KH_STRIDE + ch * 8) * 2,
                       kg + (size_t)r * HH + ch * 8);
        }
        #pragma unroll
        for (int p = 0; p < 8; p++) {
            int idx = tid + p * 128;
            int h = idx >> 3, ch = idx & 7;
            cp_async16(Vt_a + (uint32_t)(buf * V_ST_H + h * VT_STRIDE + ch * 8) * 2,
                       vtbase + (size_t)h * TT + s * 64 + ch * 8);
        }
        cp_async_commit();
    };

    issue_stage(0);
    if (nkt > 1) issue_stage(1);

    uint32_t qfr[8][4];
    {
        const uint32_t* qg0 = reinterpret_cast<const uint32_t*>(
            g_qh + ((size_t)b * TT + q0 + r0l) * HH);
        const uint32_t* qg1 = reinterpret_cast<const uint32_t*>(
            g_qh + ((size_t)b * TT + q0 + r1l) * HH);
        #pragma unroll
        for (int ks = 0; ks < 8; ks++) {
            qfr[ks][0] = qg0[8 * ks + t];
            qfr[ks][1] = qg1[8 * ks + t];
            qfr[ks][2] = qg0[8 * ks + t + 4];
            qfr[ks][3] = qg1[8 * ks + t + 4];
        }
    }

    float m0 = -INFINITY, m1 = -INFINITY, l0 = 0.0f, l1 = 0.0f;
    float oacc[16][4];
    #pragma unroll
    for (int nt = 0; nt < 16; nt++)
        #pragma unroll
        for (int e = 0; e < 4; e++) oacc[nt][e] = 0.0f;

    for (int kt = 0; kt < nkt; kt++) {
        const int buf = kt & 1;
        const uint32_t* Ks32 = reinterpret_cast<const uint32_t*>(Ksh + buf * K_ST_H);
        const uint32_t* Vt32 = reinterpret_cast<const uint32_t*>(Vth + buf * V_ST_H);

        if (kt + 1 < nkt) cp_async_wait_1(); else cp_async_wait_all();
        __syncthreads();

        float sacc[8][4];
        #pragma unroll
        for (int nt = 0; nt < 8; nt++)
            #pragma unroll
            for (int e = 0; e < 4; e++) sacc[nt][e] = 0.0f;

        #pragma unroll
        for (int ks = 0; ks < 8; ks++) {
            #pragma unroll
            for (int nt = 0; nt < 8; nt++) {
                const int n = nt * 8 + g;
                mma16(sacc[nt], qfr[ks],
                      Ks32[68 * n + 8 * ks + t],
                      Ks32[68 * n + 8 * ks + t + 4]);
            }
        }

        if (kt == qt) {
            #pragma unroll
            for (int nt = 0; nt < 8; nt++) {
                const int cl = nt * 8 + 2 * t;
                if (cl     > r0l) sacc[nt][0] = -INFINITY;
                if (cl + 1 > r0l) sacc[nt][1] = -INFINITY;
                if (cl     > r1l) sacc[nt][2] = -INFINITY;
                if (cl + 1 > r1l) sacc[nt][3] = -INFINITY;
            }
        }

        float mx0 = -INFINITY, mx1 = -INFINITY;
        #pragma unroll
        for (int nt = 0; nt < 8; nt++) {
            mx0 = fmaxf(mx0, fmaxf(sacc[nt][0], sacc[nt][1]));
            mx1 = fmaxf(mx1, fmaxf(sacc[nt][2], sacc[nt][3]));
        }
        mx0 = fmaxf(mx0, __shfl_xor_sync(0xffffffffu, mx0, 1));
        mx0 = fmaxf(mx0, __shfl_xor_sync(0xffffffffu, mx0, 2));
        mx1 = fmaxf(mx1, __shfl_xor_sync(0xffffffffu, mx1, 1));
        mx1 = fmaxf(mx1, __shfl_xor_sync(0xffffffffu, mx1, 2));

        const float m0n = fmaxf(m0, mx0);
        const float m1n = fmaxf(m1, mx1);
        const float c0 = __expf(m0 - m0n);
        const float c1 = __expf(m1 - m1n);

        float s0 = 0.0f, s1 = 0.0f;
        #pragma unroll
        for (int nt = 0; nt < 8; nt++) {
            sacc[nt][0] = __expf(sacc[nt][0] - m0n);
            sacc[nt][1] = __expf(sacc[nt][1] - m0n);
            sacc[nt][2] = __expf(sacc[nt][2] - m1n);
            sacc[nt][3] = __expf(sacc[nt][3] - m1n);
            s0 += sacc[nt][0] + sacc[nt][1];
            s1 += sacc[nt][2] + sacc[nt][3];
        }
        s0 += __shfl_xor_sync(0xffffffffu, s0, 1);
        s0 += __shfl_xor_sync(0xffffffffu, s0, 2);
        s1 += __shfl_xor_sync(0xffffffffu, s1, 1);
        s1 += __shfl_xor_sync(0xffffffffu, s1, 2);

        l0 = l0 * c0 + s0;
        l1 = l1 * c1 + s1;
        m0 = m0n;
        m1 = m1n;

        #pragma unroll
        for (int nt = 0; nt < 16; nt++) {
            oacc[nt][0] *= c0; oacc[nt][1] *= c0;
            oacc[nt][2] *= c1; oacc[nt][3] *= c1;
        }

        #pragma unroll
        for (int kk = 0; kk < 4; kk++) {
            uint32_t afr[4];
            afr[0] = packh2(sacc[2 * kk][0],     sacc[2 * kk][1]);
            afr[1] = packh2(sacc[2 * kk][2],     sacc[2 * kk][3]);
            afr[2] = packh2(sacc[2 * kk + 1][0], sacc[2 * kk + 1][1]);
            afr[3] = packh2(sacc[2 * kk + 1][2], sacc[2 * kk + 1][3]);
            #pragma unroll
            for (int nt = 0; nt < 16; nt++) {
                const int n = nt * 8 + g;
                mma16(oacc[nt], afr,
                      Vt32[36 * n + 8 * kk + t],
                      Vt32[36 * n + 8 * kk + t + 4]);
            }
        }

        if (kt + 2 < nkt) {
            __syncthreads();
            issue_stage(kt + 2);
        }
    }

    const float inv0 = 1.0f / l0;
    const float inv1 = 1.0f / l1;
    float* og = out + ((size_t)b * TT + q0) * HH;
    #pragma unroll
    for (int nt = 0; nt < 16; nt++) {
        const int col = nt * 8 + 2 * t;
        *reinterpret_cast<float2*>(&og[(size_t)r0l * HH + col]) =
            make_float2(oacc[nt][0] * inv0, oacc[nt][1] * inv0);
        *reinterpret_cast<float2*>(&og[(size_t)r1l * HH + col]) =
            make_float2(oacc[nt][2] * inv1, oacc[nt][3] * inv1);
    }
}

// ===========================================================================
// Launch
// ===========================================================================
extern "C" void kernel_launch(void* const* d_in, const int* in_sizes, int n_in,
                              void* d_out, int out_size)
{
    const float* x  = (const float*)d_in[0];
    const float* Wq = (const float*)d_in[1];
    const float* Wk = (const float*)d_in[2];
    const float* Wv = (const float*)d_in[3];
    float* out = (float*)d_out;

    cudaFuncSetAttribute(qkv_fused_kernel,
                         cudaFuncAttributeMaxDynamicSharedMemorySize, QKV_SMEM);
    cudaFuncSetAttribute(attn_fa2_kernel,
                         cudaFuncAttributeMaxDynamicSharedMemorySize, ATTN_SMEM);

    conv_w_kernel<<<dim3(NCH, 3), 256>>>(Wq, Wk, Wv);
    qkv_fused_kernel<<<TT * BB / 128, 256, QKV_SMEM>>>(x);
    attn_fa2_kernel<<<dim3(TT / 64, BB), 128, ATTN_SMEM>>>(out);
}

// round 16
// speedup vs baseline: 1.8576x; 1.0064x over previous
#include <cuda_runtime.h>
#include <cuda_fp16.h>
#include <cstdint>
#include <math.h>

#define BB 16
#define TT 2048
#define CC 768
#define HH 128

// g_wh: W^T fp16, per weight [n=128][k=768], k permuted in 32-half chunks
// (pos16 word permutation), Wq pre-scaled.
__device__ __half g_wh[3 * CC * HH];
// Attention inputs, fp16:
//   g_qh, g_kh: [b][t][h] row-major (Q pre-scaled)
//   g_vT:       [b][h][t] transposed
__device__ __half g_qh[BB * TT * HH];
__device__ __half g_kh[BB * TT * HH];
__device__ __half g_vT[BB * HH * TT];

// ---------------------------------------------------------------------------
// helpers
// ---------------------------------------------------------------------------
__device__ __forceinline__ uint32_t packh2(float lo, float hi) {
    uint32_t d;
    asm("cvt.rn.f16x2.f32 %0, %1, %2;" : "=r"(d) : "f"(hi), "f"(lo));
    return d;
}

__device__ __forceinline__ void mma16(float* d, const uint32_t* a,
                                      uint32_t b0, uint32_t b1) {
    asm volatile(
        "mma.sync.aligned.m16n8k16.row.col.f32.f16.f16.f32 "
        "{%0,%1,%2,%3}, {%4,%5,%6,%7}, {%8,%9}, {%0,%1,%2,%3};"
        : "+f"(d[0]), "+f"(d[1]), "+f"(d[2]), "+f"(d[3])
        : "r"(a[0]), "r"(a[1]), "r"(a[2]), "r"(a[3]),
          "r"(b0), "r"(b1));
}

__device__ __forceinline__ void cp_async16(uint32_t smem_dst, const void* gmem_src) {
    asm volatile("cp.async.cg.shared.global [%0], [%1], 16;"
                 :: "r"(smem_dst), "l"(gmem_src) : "memory");
}
__device__ __forceinline__ void cp_async_commit() {
    asm volatile("cp.async.commit_group;" ::: "memory");
}
__device__ __forceinline__ void cp_async_wait_all() {
    asm volatile("cp.async.wait_group 0;" ::: "memory");
}
__device__ __forceinline__ void cp_async_wait_1() {
    asm volatile("cp.async.wait_group 1;" ::: "memory");
}

__device__ __forceinline__ uint32_t smem_u32(const void* p) {
    uint32_t a;
    asm("{ .reg .u64 t; cvta.to.shared.u64 t, %1; cvt.u32.u64 %0, t; }"
        : "=r"(a) : "l"(p));
    return a;
}

__device__ __forceinline__ int pos16(int w) {
    return (w & 3) * 4 + ((w >> 3) & 1) * 2 + ((w >> 2) & 1);
}

// ===========================================================================
// Kernel 0: build g_wh = W^T fp16 with permuted k (Wq pre-scaled, rn).
// (unchanged from R15 — known good at ~6 us)
// ===========================================================================
__global__ __launch_bounds__(256) void conv_w_kernel(
    const float* __restrict__ Wq,
    const float* __restrict__ Wk,
    const float* __restrict__ Wv)
{
    __shared__ unsigned short sm_t[32 * 130];   // [kk][n], stride 130

    const int chunk = blockIdx.x;        // 0..23 (32-half chunks)
    const int w     = blockIdx.y;        // 0..2
    const int k0    = chunk * 32;
    const int tid   = threadIdx.x;
    const float* W  = (w == 0) ? Wq : (w == 1) ? Wk : Wv;
    const float s   = (w == 0) ? 0.03608439182435161f : 1.0f;

    #pragma unroll
    for (int p = 0; p < 16; p++) {
        int idx = tid + p * 256;
        int kk = idx >> 7, n = idx & 127;
        float v = W[(size_t)(k0 + kk) * HH + n] * s;
        __half hv = __float2half_rn(v);
        sm_t[kk * 130 + n] = *reinterpret_cast<unsigned short*>(&hv);
    }
    __syncthreads();

    if (tid < 128) {
        const int n = tid;
        uint32_t row[16];
        #pragma unroll
        for (int word = 0; word < 16; word++) {
            uint32_t lo = sm_t[(2 * word)     * 130 + n];
            uint32_t hi = sm_t[(2 * word + 1) * 130 + n];
            row[pos16(word)] = lo | (hi << 16);
        }
        uint4* dst = reinterpret_cast<uint4*>(
            g_wh + ((size_t)w * HH + n) * CC + chunk * 32);
        dst[0] = make_uint4(row[0],  row[1],  row[2],  row[3]);
        dst[1] = make_uint4(row[4],  row[5],  row[6],  row[7]);
        dst[2] = make_uint4(row[8],  row[9],  row[10], row[11]);
        dst[3] = make_uint4(row[12], row[13], row[14], row[15]);
    }
}

// ===========================================================================
// Kernel 1: fused QKV projection, fp16 m16n8k16, 64-wide K chunks,
// 2-stage cp.async. 12 iterations (half the syncs of R15).
// ===========================================================================
#define KC 64
#define NCH 12   // 768 / 64

#define AS_STRIDE 68                               // fp32 words per A row (64+4)
#define BROW_WORDS 36                              // 32 data + 4 pad per n-row
#define A_BUF (128 * AS_STRIDE)                    // 8704 words
#define B_ALL (3 * 128 * BROW_WORDS)               // 13824 words
#define STAGE_WORDS (A_BUF + B_ALL)                // 22528 words
#define QKV_SMEM (2 * STAGE_WORDS * 4)             // 180224 B

__global__ __launch_bounds__(256) void qkv_fused_kernel(const float* __restrict__ x)
{
    extern __shared__ uint32_t sm_u[];
    const uint32_t sm_a = smem_u32(sm_u);

    const int tid  = threadIdx.x;
    const int lane = tid & 31;
    const int wid  = tid >> 5;
    const int g = lane >> 2;
    const int t = lane & 3;
    const int wr = wid & 3;
    const int wc = wid >> 2;
    const int m0 = blockIdx.x * 128;

    float acc[3][2][8][4];
    #pragma unroll
    for (int w = 0; w < 3; w++)
        #pragma unroll
        for (int mt = 0; mt < 2; mt++)
            #pragma unroll
            for (int nt = 0; nt < 8; nt++)
                #pragma unroll
                for (int e = 0; e < 4; e++) acc[w][mt][nt][e] = 0.0f;

    auto issue_stage = [&](int c, int buf) {
        const uint32_t base = sm_a + (uint32_t)buf * STAGE_WORDS * 4;
        // A: 128 rows x 64 fp32 = 2048 16B chunks, 8/thread
        const float* xg = x + (size_t)m0 * CC + c * KC;
        #pragma unroll
        for (int p = 0; p < 8; p++) {
            int idx = tid + p * 256;
            int m = idx >> 4, k4 = (idx & 15) << 2;
            cp_async16(base + (uint32_t)(m * AS_STRIDE + k4) * 4,
                       xg + (size_t)m * CC + k4);
        }
        // B: 3 x 128 n-rows x 128B (32 words) = 3072 chunks, 12/thread
        #pragma unroll
        for (int p = 0; p < 12; p++) {
            int idx = tid + p * 256;
            int n_all = idx >> 3;           // 0..383
            int ch = idx & 7;               // 16B chunk within 128B row
            cp_async16(base + (uint32_t)(A_BUF + n_all * BROW_WORDS + ch * 4) * 4,
                       g_wh + (size_t)n_all * CC + c * KC + ch * 8);
        }
        cp_async_commit();
    };

    issue_stage(0, 0);

    for (int c = 0; c < NCH; c++) {
        const int buf = c & 1;
        __syncthreads();
        if (c + 1 < NCH) {
            issue_stage(c + 1, buf ^ 1);
            cp_async_wait_1();
        } else {
            cp_async_wait_all();
        }
        __syncthreads();

        const uint32_t* As = sm_u + buf * STAGE_WORDS;
        const uint32_t* Bs = As + A_BUF;
        const float2* A2 = reinterpret_cast<const float2*>(As);  // 34 f2/row

        // A fragments for 4 k16-steps (fp32 -> fp16 pack)
        uint32_t afr[4][2][4];
        #pragma unroll
        for (int ks = 0; ks < 4; ks++) {
            #pragma unroll
            for (int mt = 0; mt < 2; mt++) {
                const int rb = wr * 32 + mt * 16;
                float2 p0 = A2[(rb + g)     * 34 + ks * 8 + t];
                float2 p1 = A2[(rb + g + 8) * 34 + ks * 8 + t];
                float2 p2 = A2[(rb + g)     * 34 + ks * 8 + t + 4];
                float2 p3 = A2[(rb + g + 8) * 34 + ks * 8 + t + 4];
                afr[ks][mt][0] = packh2(p0.x, p0.y);
                afr[ks][mt][1] = packh2(p1.x, p1.y);
                afr[ks][mt][2] = packh2(p2.x, p2.y);
                afr[ks][mt][3] = packh2(p3.x, p3.y);
            }
        }

        #pragma unroll
        for (int w = 0; w < 3; w++) {
            #pragma unroll
            for (int nt = 0; nt < 8; nt++) {
                const int n_all = w * 128 + wc * 64 + nt * 8 + g;
                uint4 bq0 = *reinterpret_cast<const uint4*>(
                    &Bs[n_all * BROW_WORDS + t * 4]);
                uint4 bq1 = *reinterpret_cast<const uint4*>(
                    &Bs[n_all * BROW_WORDS + 16 + t * 4]);
                mma16(acc[w][0][nt], afr[0][0], bq0.x, bq0.y);
                mma16(acc[w][1][nt], afr[0][1], bq0.x, bq0.y);
                mma16(acc[w][0][nt], afr[1][0], bq0.z, bq0.w);
                mma16(acc[w][1][nt], afr[1][1], bq0.z, bq0.w);
                mma16(acc[w][0][nt], afr[2][0], bq1.x, bq1.y);
                mma16(acc[w][1][nt], afr[2][1], bq1.x, bq1.y);
                mma16(acc[w][0][nt], afr[3][0], bq1.z, bq1.w);
                mma16(acc[w][1][nt], afr[3][1], bq1.z, bq1.w);
            }
        }
    }

    // ---- epilogue part 1: Q/K row-major half2 (coalesced) ----
    __half* outs2[2] = {g_qh, g_kh};
    #pragma unroll
    for (int mt = 0; mt < 2; mt++) {
        const int r0 = m0 + wr * 32 + mt * 16 + g;
        #pragma unroll
        for (int nt = 0; nt < 8; nt++) {
            const int col = wc * 64 + nt * 8 + 2 * t;
            #pragma unroll
            for (int w = 0; w < 2; w++) {
                __half* outw = outs2[w];
                *reinterpret_cast<uint32_t*>(&outw[(size_t)r0 * HH + col]) =
                    packh2(acc[w][mt][nt][0], acc[w][mt][nt][1]);
                *reinterpret_cast<uint32_t*>(&outw[(size_t)(r0 + 8) * HH + col]) =
                    packh2(acc[w][mt][nt][2], acc[w][mt][nt][3]);
            }
        }
    }

    // ---- epilogue part 2: V transposed through smem, coalesced writes ----
    __syncthreads();
    __half* vt_sm = reinterpret_cast<__half*>(sm_u);    // [128 cols][136]
    #pragma unroll
    for (int mt = 0; mt < 2; mt++) {
        const int r = wr * 32 + mt * 16 + g;
        #pragma unroll
        for (int nt = 0; nt < 8; nt++) {
            const int col = wc * 64 + nt * 8 + 2 * t;
            vt_sm[col * 136 + r]           = __float2half_rn(acc[2][mt][nt][0]);
            vt_sm[(col + 1) * 136 + r]     = __float2half_rn(acc[2][mt][nt][1]);
            vt_sm[col * 136 + r + 8]       = __float2half_rn(acc[2][mt][nt][2]);
            vt_sm[(col + 1) * 136 + r + 8] = __float2half_rn(acc[2][mt][nt][3]);
        }
    }
    __syncthreads();
    {
        const int bq = m0 >> 11;
        const int tp0 = m0 & 2047;
        #pragma unroll
        for (int p = 0; p < 8; p++) {
            int idx = tid + p * 256;
            int h = idx >> 4, ch = idx & 15;
            *reinterpret_cast<uint4*>(
                &g_vT[((size_t)bq * HH + h) * TT + tp0 + ch * 8]) =
                *reinterpret_cast<const uint4*>(&vt_sm[h * 136 + ch * 8]);
        }
    }
}

// ===========================================================================
// Kernel 2: fp16 causal flash attention, double-buffered {K,V} stages
// (unchanged from R14/R15 — known good).
// ===========================================================================
#define KH_STRIDE 136
#define VT_STRIDE 72
#define K_ST_H (64 * KH_STRIDE)
#define V_ST_H (128 * VT_STRIDE)
#define ATTN_SMEM ((2 * K_ST_H + 2 * V_ST_H) * 2)   // 71680 B

__global__ __launch_bounds__(128, 2) void attn_fa2_kernel(float* __restrict__ out)
{
    extern __shared__ __half smh[];
    __half* Ksh = smh;                    // [2][64][136]
    __half* Vth = smh + 2 * K_ST_H;       // [2][128][72]
    const uint32_t Ks_a = smem_u32(Ksh);
    const uint32_t Vt_a = smem_u32(Vth);

    const int b  = blockIdx.y;
    const int qt = (int)gridDim.x - 1 - (int)blockIdx.x;
    const int q0 = qt * 64;
    const int tid  = threadIdx.x;
    const int wid  = tid >> 5;
    const int lane = tid & 31;
    const int g = lane >> 2;
    const int t = lane & 3;

    const int r0l = wid * 16 + g;
    const int r1l = r0l + 8;

    const __half* kbase  = g_kh + (size_t)b * TT * HH;
    const __half* vtbase = g_vT + (size_t)b * HH * TT;
    const int nkt = qt + 1;

    auto issue_stage = [&](int s) {
        const int buf = s & 1;
        const __half* kg = kbase + (size_t)s * 64 * HH;
        #pragma unroll
        for (int p = 0; p < 8; p++) {
            int idx = tid + p * 128;
            int r = idx >> 4, ch = idx & 15;
            cp_async16(Ks_a + (uint32_t)(buf * K_ST_H + r * KH_STRIDE + ch * 8) * 2,
                       kg + (size_t)r * HH + ch * 8);
        }
        #pragma unroll
        for (int p = 0; p < 8; p++) {
            int idx = tid + p * 128;
            int h = idx >> 3, ch = idx & 7;
            cp_async16(Vt_a + (uint32_t)(buf * V_ST_H + h * VT_STRIDE + ch * 8) * 2,
                       vtbase + (size_t)h * TT + s * 64 + ch * 8);
        }
        cp_async_commit();
    };

    issue_stage(0);
    if (nkt > 1) issue_stage(1);

    uint32_t qfr[8][4];
    {
        const uint32_t* qg0 = reinterpret_cast<const uint32_t*>(
            g_qh + ((size_t)b * TT + q0 + r0l) * HH);
        const uint32_t* qg1 = reinterpret_cast<const uint32_t*>(
            g_qh + ((size_t)b * TT + q0 + r1l) * HH);
        #pragma unroll
        for (int ks = 0; ks < 8; ks++) {
            qfr[ks][0] = qg0[8 * ks + t];
            qfr[ks][1] = qg1[8 * ks + t];
            qfr[ks][2] = qg0[8 * ks + t + 4];
            qfr[ks][3] = qg1[8 * ks + t + 4];
        }
    }

    float m0 = -INFINITY, m1 = -INFINITY, l0 = 0.0f, l1 = 0.0f;
    float oacc[16][4];
    #pragma unroll
    for (int nt = 0; nt < 16; nt++)
        #pragma unroll
        for (int e = 0; e < 4; e++) oacc[nt][e] = 0.0f;

    for (int kt = 0; kt < nkt; kt++) {
        const int buf = kt & 1;
        const uint32_t* Ks32 = reinterpret_cast<const uint32_t*>(Ksh + buf * K_ST_H);
        const uint32_t* Vt32 = reinterpret_cast<const uint32_t*>(Vth + buf * V_ST_H);

        if (kt + 1 < nkt) cp_async_wait_1(); else cp_async_wait_all();
        __syncthreads();

        float sacc[8][4];
        #pragma unroll
        for (int nt = 0; nt < 8; nt++)
            #pragma unroll
            for (int e = 0; e < 4; e++) sacc[nt][e] = 0.0f;

        #pragma unroll
        for (int ks = 0; ks < 8; ks++) {
            #pragma unroll
            for (int nt = 0; nt < 8; nt++) {
                const int n = nt * 8 + g;
                mma16(sacc[nt], qfr[ks],
                      Ks32[68 * n + 8 * ks + t],
                      Ks32[68 * n + 8 * ks + t + 4]);
            }
        }

        if (kt == qt) {
            #pragma unroll
            for (int nt = 0; nt < 8; nt++) {
                const int cl = nt * 8 + 2 * t;
                if (cl     > r0l) sacc[nt][0] = -INFINITY;
                if (cl + 1 > r0l) sacc[nt][1] = -INFINITY;
                if (cl     > r1l) sacc[nt][2] = -INFINITY;
                if (cl + 1 > r1l) sacc[nt][3] = -INFINITY;
            }
        }

        float mx0 = -INFINITY, mx1 = -INFINITY;
        #pragma unroll
        for (int nt = 0; nt < 8; nt++) {
            mx0 = fmaxf(mx0, fmaxf(sacc[nt][0], sacc[nt][1]));
            mx1 = fmaxf(mx1, fmaxf(sacc[nt][2], sacc[nt][3]));
        }
        mx0 = fmaxf(mx0, __shfl_xor_sync(0xffffffffu, mx0, 1));
        mx0 = fmaxf(mx0, __shfl_xor_sync(0xffffffffu, mx0, 2));
        mx1 = fmaxf(mx1, __shfl_xor_sync(0xffffffffu, mx1, 1));
        mx1 = fmaxf(mx1, __shfl_xor_sync(0xffffffffu, mx1, 2));

        const float m0n = fmaxf(m0, mx0);
        const float m1n = fmaxf(m1, mx1);
        const float c0 = __expf(m0 - m0n);
        const float c1 = __expf(m1 - m1n);

        float s0 = 0.0f, s1 = 0.0f;
        #pragma unroll
        for (int nt = 0; nt < 8; nt++) {
            sacc[nt][0] = __expf(sacc[nt][0] - m0n);
            sacc[nt][1] = __expf(sacc[nt][1] - m0n);
            sacc[nt][2] = __expf(sacc[nt][2] - m1n);
            sacc[nt][3] = __expf(sacc[nt][3] - m1n);
            s0 += sacc[nt][0] + sacc[nt][1];
            s1 += sacc[nt][2] + sacc[nt][3];
        }
        s0 += __shfl_xor_sync(0xffffffffu, s0, 1);
        s0 += __shfl_xor_sync(0xffffffffu, s0, 2);
        s1 += __shfl_xor_sync(0xffffffffu, s1, 1);
        s1 += __shfl_xor_sync(0xffffffffu, s1, 2);

        l0 = l0 * c0 + s0;
        l1 = l1 * c1 + s1;
        m0 = m0n;
        m1 = m1n;

        #pragma unroll
        for (int nt = 0; nt < 16; nt++) {
            oacc[nt][0] *= c0; oacc[nt][1] *= c0;
            oacc[nt][2] *= c1; oacc[nt][3] *= c1;
        }

        #pragma unroll
        for (int kk = 0; kk < 4; kk++) {
            uint32_t afr[4];
            afr[0] = packh2(sacc[2 * kk][0],     sacc[2 * kk][1]);
            afr[1] = packh2(sacc[2 * kk][2],     sacc[2 * kk][3]);
            afr[2] = packh2(sacc[2 * kk + 1][0], sacc[2 * kk + 1][1]);
            afr[3] = packh2(sacc[2 * kk + 1][2], sacc[2 * kk + 1][3]);
            #pragma unroll
            for (int nt = 0; nt < 16; nt++) {
                const int n = nt * 8 + g;
                mma16(oacc[nt], afr,
                      Vt32[36 * n + 8 * kk + t],
                      Vt32[36 * n + 8 * kk + t + 4]);
            }
        }

        if (kt + 2 < nkt) {
            __syncthreads();
            issue_stage(kt + 2);
        }
    }

    const float inv0 = 1.0f / l0;
    const float inv1 = 1.0f / l1;
    float* og = out + ((size_t)b * TT + q0) * HH;
    #pragma unroll
    for (int nt = 0; nt < 16; nt++) {
        const int col = nt * 8 + 2 * t;
        *reinterpret_cast<float2*>(&og[(size_t)r0l * HH + col]) =
            make_float2(oacc[nt][0] * inv0, oacc[nt][1] * inv0);
        *reinterpret_cast<float2*>(&og[(size_t)r1l * HH + col]) =
            make_float2(oacc[nt][2] * inv1, oacc[nt][3] * inv1);
    }
}

// ===========================================================================
// Launch
// ===========================================================================
extern "C" void kernel_launch(void* const* d_in, const int* in_sizes, int n_in,
                              void* d_out, int out_size)
{
    const float* x  = (const float*)d_in[0];
    const float* Wq = (const float*)d_in[1];
    const float* Wk = (const float*)d_in[2];
    const float* Wv = (const float*)d_in[3];
    float* out = (float*)d_out;

    cudaFuncSetAttribute(qkv_fused_kernel,
                         cudaFuncAttributeMaxDynamicSharedMemorySize, QKV_SMEM);
    cudaFuncSetAttribute(attn_fa2_kernel,
                         cudaFuncAttributeMaxDynamicSharedMemorySize, ATTN_SMEM);

    conv_w_kernel<<<dim3(24, 3), 256>>>(Wq, Wk, Wv);
    qkv_fused_kernel<<<TT * BB / 128, 256, QKV_SMEM>>>(x);
    attn_fa2_kernel<<<dim3(TT / 64, BB), 128, ATTN_SMEM>>>(out);
}

// round 17
// speedup vs baseline: 2.0069x; 1.0804x over previous
#include <cuda_runtime.h>
#include <cuda_fp16.h>
#include <cstdint>
#include <math.h>

#define BB 16
#define TT 2048
#define CC 768
#define HH 128

// g_wh: W^T fp16, per weight [n=128][k=768], pos16-permuted per 32-half chunk.
__device__ __half g_wh[3 * CC * HH];
// Attention inputs, fp16, pos16-permuted (word granularity, within 64B chunks):
//   g_qh, g_kh: [b][t][h] rows, head-dim words permuted per 16-word chunk
//   g_vT:       [b][h][t] rows, token words permuted per 16-word chunk
__device__ __half g_qh[BB * TT * HH];
__device__ __half g_kh[BB * TT * HH];
__device__ __half g_vT[BB * HH * TT];

// ---------------------------------------------------------------------------
// helpers
// ---------------------------------------------------------------------------
__device__ __forceinline__ uint32_t packh2(float lo, float hi) {
    uint32_t d;
    asm("cvt.rn.f16x2.f32 %0, %1, %2;" : "=r"(d) : "f"(hi), "f"(lo));
    return d;
}

__device__ __forceinline__ void mma16(float* d, const uint32_t* a,
                                      uint32_t b0, uint32_t b1) {
    asm volatile(
        "mma.sync.aligned.m16n8k16.row.col.f32.f16.f16.f32 "
        "{%0,%1,%2,%3}, {%4,%5,%6,%7}, {%8,%9}, {%0,%1,%2,%3};"
        : "+f"(d[0]), "+f"(d[1]), "+f"(d[2]), "+f"(d[3])
        : "r"(a[0]), "r"(a[1]), "r"(a[2]), "r"(a[3]),
          "r"(b0), "r"(b1));
}

__device__ __forceinline__ void cp_async16(uint32_t smem_dst, const void* gmem_src) {
    asm volatile("cp.async.cg.shared.global [%0], [%1], 16;"
                 :: "r"(smem_dst), "l"(gmem_src) : "memory");
}
__device__ __forceinline__ void cp_async_commit() {
    asm volatile("cp.async.commit_group;" ::: "memory");
}
__device__ __forceinline__ void cp_async_wait_all() {
    asm volatile("cp.async.wait_group 0;" ::: "memory");
}
__device__ __forceinline__ void cp_async_wait_1() {
    asm volatile("cp.async.wait_group 1;" ::: "memory");
}

__device__ __forceinline__ uint32_t smem_u32(const void* p) {
    uint32_t a;
    asm("{ .reg .u64 t; cvta.to.shared.u64 t, %1; cvt.u32.u64 %0, t; }"
        : "=r"(a) : "l"(p));
    return a;
}

// word permutation within a 16-word chunk: thread t's 4 fragment words
// (2 k16-steps x {b0,b1}) land contiguously at 4t..4t+3.
__device__ __forceinline__ int pos16(int w) {
    return (w & 3) * 4 + ((w >> 3) & 1) * 2 + ((w >> 2) & 1);
}
// permute a word index within its 16-word chunk
__device__ __forceinline__ int permw(int w) {
    return (w & ~15) | pos16(w & 15);
}
// permute a half (token) index: word-granularity permutation
__device__ __forceinline__ int permh(int r) {
    return permw(r >> 1) * 2 + (r & 1);
}

// ===========================================================================
// Kernel 0: build g_wh = W^T fp16 with permuted k (Wq pre-scaled, rn).
// (unchanged — known good at ~6 us)
// ===========================================================================
__global__ __launch_bounds__(256) void conv_w_kernel(
    const float* __restrict__ Wq,
    const float* __restrict__ Wk,
    const float* __restrict__ Wv)
{
    __shared__ unsigned short sm_t[32 * 130];

    const int chunk = blockIdx.x;
    const int w     = blockIdx.y;
    const int k0    = chunk * 32;
    const int tid   = threadIdx.x;
    const float* W  = (w == 0) ? Wq : (w == 1) ? Wk : Wv;
    const float s   = (w == 0) ? 0.03608439182435161f : 1.0f;

    #pragma unroll
    for (int p = 0; p < 16; p++) {
        int idx = tid + p * 256;
        int kk = idx >> 7, n = idx & 127;
        float v = W[(size_t)(k0 + kk) * HH + n] * s;
        __half hv = __float2half_rn(v);
        sm_t[kk * 130 + n] = *reinterpret_cast<unsigned short*>(&hv);
    }
    __syncthreads();

    if (tid < 128) {
        const int n = tid;
        uint32_t row[16];
        #pragma unroll
        for (int word = 0; word < 16; word++) {
            uint32_t lo = sm_t[(2 * word)     * 130 + n];
            uint32_t hi = sm_t[(2 * word + 1) * 130 + n];
            row[pos16(word)] = lo | (hi << 16);
        }
        uint4* dst = reinterpret_cast<uint4*>(
            g_wh + ((size_t)w * HH + n) * CC + chunk * 32);
        dst[0] = make_uint4(row[0],  row[1],  row[2],  row[3]);
        dst[1] = make_uint4(row[4],  row[5],  row[6],  row[7]);
        dst[2] = make_uint4(row[8],  row[9],  row[10], row[11]);
        dst[3] = make_uint4(row[12], row[13], row[14], row[15]);
    }
}

// ===========================================================================
// Kernel 1: fused QKV projection (R16 mainloop). Epilogue writes Q/K/V in
// pos16-permuted layouts (word-granularity, coalescing preserved).
// ===========================================================================
#define KC 64
#define NCH 12

#define AS_STRIDE 68
#define BROW_WORDS 36
#define A_BUF (128 * AS_STRIDE)
#define B_ALL (3 * 128 * BROW_WORDS)
#define STAGE_WORDS (A_BUF + B_ALL)
#define QKV_SMEM (2 * STAGE_WORDS * 4)

__global__ __launch_bounds__(256) void qkv_fused_kernel(const float* __restrict__ x)
{
    extern __shared__ uint32_t sm_u[];
    const uint32_t sm_a = smem_u32(sm_u);

    const int tid  = threadIdx.x;
    const int lane = tid & 31;
    const int wid  = tid >> 5;
    const int g = lane >> 2;
    const int t = lane & 3;
    const int wr = wid & 3;
    const int wc = wid >> 2;
    const int m0 = blockIdx.x * 128;

    float acc[3][2][8][4];
    #pragma unroll
    for (int w = 0; w < 3; w++)
        #pragma unroll
        for (int mt = 0; mt < 2; mt++)
            #pragma unroll
            for (int nt = 0; nt < 8; nt++)
                #pragma unroll
                for (int e = 0; e < 4; e++) acc[w][mt][nt][e] = 0.0f;

    auto issue_stage = [&](int c, int buf) {
        const uint32_t base = sm_a + (uint32_t)buf * STAGE_WORDS * 4;
        const float* xg = x + (size_t)m0 * CC + c * KC;
        #pragma unroll
        for (int p = 0; p < 8; p++) {
            int idx = tid + p * 256;
            int m = idx >> 4, k4 = (idx & 15) << 2;
            cp_async16(base + (uint32_t)(m * AS_STRIDE + k4) * 4,
                       xg + (size_t)m * CC + k4);
        }
        #pragma unroll
        for (int p = 0; p < 12; p++) {
            int idx = tid + p * 256;
            int n_all = idx >> 3;
            int ch = idx & 7;
            cp_async16(base + (uint32_t)(A_BUF + n_all * BROW_WORDS + ch * 4) * 4,
                       g_wh + (size_t)n_all * CC + c * KC + ch * 8);
        }
        cp_async_commit();
    };

    issue_stage(0, 0);

    for (int c = 0; c < NCH; c++) {
        const int buf = c & 1;
        __syncthreads();
        if (c + 1 < NCH) {
            issue_stage(c + 1, buf ^ 1);
            cp_async_wait_1();
        } else {
            cp_async_wait_all();
        }
        __syncthreads();

        const uint32_t* As = sm_u + buf * STAGE_WORDS;
        const uint32_t* Bs = As + A_BUF;
        const float2* A2 = reinterpret_cast<const float2*>(As);

        uint32_t afr[4][2][4];
        #pragma unroll
        for (int ks = 0; ks < 4; ks++) {
            #pragma unroll
            for (int mt = 0; mt < 2; mt++) {
                const int rb = wr * 32 + mt * 16;
                float2 p0 = A2[(rb + g)     * 34 + ks * 8 + t];
                float2 p1 = A2[(rb + g + 8) * 34 + ks * 8 + t];
                float2 p2 = A2[(rb + g)     * 34 + ks * 8 + t + 4];
                float2 p3 = A2[(rb + g + 8) * 34 + ks * 8 + t + 4];
                afr[ks][mt][0] = packh2(p0.x, p0.y);
                afr[ks][mt][1] = packh2(p1.x, p1.y);
                afr[ks][mt][2] = packh2(p2.x, p2.y);
                afr[ks][mt][3] = packh2(p3.x, p3.y);
            }
        }

        #pragma unroll
        for (int w = 0; w < 3; w++) {
            #pragma unroll
            for (int nt = 0; nt < 8; nt++) {
                const int n_all = w * 128 + wc * 64 + nt * 8 + g;
                uint4 bq0 = *reinterpret_cast<const uint4*>(
                    &Bs[n_all * BROW_WORDS + t * 4]);
                uint4 bq1 = *reinterpret_cast<const uint4*>(
                    &Bs[n_all * BROW_WORDS + 16 + t * 4]);
                mma16(acc[w][0][nt], afr[0][0], bq0.x, bq0.y);
                mma16(acc[w][1][nt], afr[0][1], bq0.x, bq0.y);
                mma16(acc[w][0][nt], afr[1][0], bq0.z, bq0.w);
                mma16(acc[w][1][nt], afr[1][1], bq0.z, bq0.w);
                mma16(acc[w][0][nt], afr[2][0], bq1.x, bq1.y);
                mma16(acc[w][1][nt], afr[2][1], bq1.x, bq1.y);
                mma16(acc[w][0][nt], afr[3][0], bq1.z, bq1.w);
                mma16(acc[w][1][nt], afr[3][1], bq1.z, bq1.w);
            }
        }
    }

    // ---- epilogue part 1: Q/K permuted-word half2 stores (coalesced within 64B) ----
    __half* outs2[2] = {g_qh, g_kh};
    #pragma unroll
    for (int mt = 0; mt < 2; mt++) {
        const int r0 = m0 + wr * 32 + mt * 16 + g;
        #pragma unroll
        for (int nt = 0; nt < 8; nt++) {
            const int wg = wc * 32 + nt * 4 + t;        // global word index
            const int dw = permw(wg);                    // permuted word
            #pragma unroll
            for (int w = 0; w < 2; w++) {
                __half* outw = outs2[w];
                *reinterpret_cast<uint32_t*>(&outw[(size_t)r0 * HH + dw * 2]) =
                    packh2(acc[w][mt][nt][0], acc[w][mt][nt][1]);
                *reinterpret_cast<uint32_t*>(&outw[(size_t)(r0 + 8) * HH + dw * 2]) =
                    packh2(acc[w][mt][nt][2], acc[w][mt][nt][3]);
            }
        }
    }

    // ---- epilogue part 2: V transposed through smem (token-permuted), coalesced ----
    __syncthreads();
    __half* vt_sm = reinterpret_cast<__half*>(sm_u);    // [128 cols][136]
    #pragma unroll
    for (int mt = 0; mt < 2; mt++) {
        const int r = wr * 32 + mt * 16 + g;
        const int fr  = permh(r);
        const int fr8 = permh(r + 8);
        #pragma unroll
        for (int nt = 0; nt < 8; nt++) {
            const int col = wc * 64 + nt * 8 + 2 * t;
            vt_sm[col * 136 + fr]        = __float2half_rn(acc[2][mt][nt][0]);
            vt_sm[(col + 1) * 136 + fr]  = __float2half_rn(acc[2][mt][nt][1]);
            vt_sm[col * 136 + fr8]       = __float2half_rn(acc[2][mt][nt][2]);
            vt_sm[(col + 1) * 136 + fr8] = __float2half_rn(acc[2][mt][nt][3]);
        }
    }
    __syncthreads();
    {
        const int bq = m0 >> 11;
        const int tp0 = m0 & 2047;
        #pragma unroll
        for (int p = 0; p < 8; p++) {
            int idx = tid + p * 256;
            int h = idx >> 4, ch = idx & 15;
            *reinterpret_cast<uint4*>(
                &g_vT[((size_t)bq * HH + h) * TT + tp0 + ch * 8]) =
                *reinterpret_cast<const uint4*>(&vt_sm[h * 136 + ch * 8]);
        }
    }
}

// ===========================================================================
// Kernel 2: fp16 causal flash attention, double-buffered {K,V} stages.
// All fragment loads vectorized (LDS.128 / LDG.128) from permuted layouts.
// K smem row = 80 words (conflict-free phases); V^T row = 48 words.
// ===========================================================================
#define KROW_W 80                        // words per K row (64 data + 16 pad)
#define VROW_W 48                        // words per V^T row (32 data + 16 pad)
#define K_ST_H (64 * KROW_W * 2)         // halfs per K stage
#define V_ST_H (128 * VROW_W * 2)        // halfs per V stage
#define ATTN_SMEM ((2 * K_ST_H + 2 * V_ST_H) * 2)   // 90112 B

__global__ __launch_bounds__(128, 2) void attn_fa2_kernel(float* __restrict__ out)
{
    extern __shared__ __half smh[];
    __half* Ksh = smh;                    // [2][64][160]
    __half* Vth = smh + 2 * K_ST_H;       // [2][128][96]
    const uint32_t Ks_a = smem_u32(Ksh);
    const uint32_t Vt_a = smem_u32(Vth);

    const int b  = blockIdx.y;
    const int qt = (int)gridDim.x - 1 - (int)blockIdx.x;
    const int q0 = qt * 64;
    const int tid  = threadIdx.x;
    const int wid  = tid >> 5;
    const int lane = tid & 31;
    const int g = lane >> 2;
    const int t = lane & 3;

    const int r0l = wid * 16 + g;
    const int r1l = r0l + 8;

    const __half* kbase  = g_kh + (size_t)b * TT * HH;
    const __half* vtbase = g_vT + (size_t)b * HH * TT;
    const int nkt = qt + 1;

    auto issue_stage = [&](int s) {
        const int buf = s & 1;
        const __half* kg = kbase + (size_t)s * 64 * HH;
        #pragma unroll
        for (int p = 0; p < 8; p++) {
            int idx = tid + p * 128;
            int r = idx >> 4, ch = idx & 15;
            cp_async16(Ks_a + (uint32_t)(buf * K_ST_H + r * (KROW_W * 2) + ch * 8) * 2,
                       kg + (size_t)r * HH + ch * 8);
        }
        #pragma unroll
        for (int p = 0; p < 8; p++) {
            int idx = tid + p * 128;
            int h = idx >> 3, ch = idx & 7;
            cp_async16(Vt_a + (uint32_t)(buf * V_ST_H + h * (VROW_W * 2) + ch * 8) * 2,
                       vtbase + (size_t)h * TT + s * 64 + ch * 8);
        }
        cp_async_commit();
    };

    issue_stage(0);
    if (nkt > 1) issue_stage(1);

    // Q fragments: LDG.128 from permuted rows (4 chunks x 2 rows)
    uint32_t qfr[8][4];
    {
        const uint4* qg0 = reinterpret_cast<const uint4*>(
            g_qh + ((size_t)b * TT + q0 + r0l) * HH);
        const uint4* qg1 = reinterpret_cast<const uint4*>(
            g_qh + ((size_t)b * TT + q0 + r1l) * HH);
        #pragma unroll
        for (int c = 0; c < 4; c++) {
            uint4 a0 = qg0[c * 4 + t];
            uint4 a1 = qg1[c * 4 + t];
            qfr[2 * c][0] = a0.x;     qfr[2 * c][2] = a0.y;
            qfr[2 * c + 1][0] = a0.z; qfr[2 * c + 1][2] = a0.w;
            qfr[2 * c][1] = a1.x;     qfr[2 * c][3] = a1.y;
            qfr[2 * c + 1][1] = a1.z; qfr[2 * c + 1][3] = a1.w;
        }
    }

    float m0 = -INFINITY, m1 = -INFINITY, l0 = 0.0f, l1 = 0.0f;
    float oacc[16][4];
    #pragma unroll
    for (int nt = 0; nt < 16; nt++)
        #pragma unroll
        for (int e = 0; e < 4; e++) oacc[nt][e] = 0.0f;

    for (int kt = 0; kt < nkt; kt++) {
        const int buf = kt & 1;
        const uint4* K4 = reinterpret_cast<const uint4*>(Ksh + buf * K_ST_H);
        const uint4* V4 = reinterpret_cast<const uint4*>(Vth + buf * V_ST_H);

        if (kt + 1 < nkt) cp_async_wait_1(); else cp_async_wait_all();
        __syncthreads();

        // ---- S = Q K^T : K-frags via LDS.128 ----
        float sacc[8][4];
        #pragma unroll
        for (int nt = 0; nt < 8; nt++)
            #pragma unroll
            for (int e = 0; e < 4; e++) sacc[nt][e] = 0.0f;

        #pragma unroll
        for (int c = 0; c < 4; c++) {
            #pragma unroll
            for (int nt = 0; nt < 8; nt++) {
                const int n = nt * 8 + g;
                uint4 kb = K4[n * (KROW_W / 4) + c * 4 + t];
                mma16(sacc[nt], qfr[2 * c],     kb.x, kb.y);
                mma16(sacc[nt], qfr[2 * c + 1], kb.z, kb.w);
            }
        }

        if (kt == qt) {
            #pragma unroll
            for (int nt = 0; nt < 8; nt++) {
                const int cl = nt * 8 + 2 * t;
                if (cl     > r0l) sacc[nt][0] = -INFINITY;
                if (cl + 1 > r0l) sacc[nt][1] = -INFINITY;
                if (cl     > r1l) sacc[nt][2] = -INFINITY;
                if (cl + 1 > r1l) sacc[nt][3] = -INFINITY;
            }
        }

        float mx0 = -INFINITY, mx1 = -INFINITY;
        #pragma unroll
        for (int nt = 0; nt < 8; nt++) {
            mx0 = fmaxf(mx0, fmaxf(sacc[nt][0], sacc[nt][1]));
            mx1 = fmaxf(mx1, fmaxf(sacc[nt][2], sacc[nt][3]));
        }
        mx0 = fmaxf(mx0, __shfl_xor_sync(0xffffffffu, mx0, 1));
        mx0 = fmaxf(mx0, __shfl_xor_sync(0xffffffffu, mx0, 2));
        mx1 = fmaxf(mx1, __shfl_xor_sync(0xffffffffu, mx1, 1));
        mx1 = fmaxf(mx1, __shfl_xor_sync(0xffffffffu, mx1, 2));

        const float m0n = fmaxf(m0, mx0);
        const float m1n = fmaxf(m1, mx1);
        const float c0 = __expf(m0 - m0n);
        const float c1 = __expf(m1 - m1n);

        float s0 = 0.0f, s1 = 0.0f;
        #pragma unroll
        for (int nt = 0; nt < 8; nt++) {
            sacc[nt][0] = __expf(sacc[nt][0] - m0n);
            sacc[nt][1] = __expf(sacc[nt][1] - m0n);
            sacc[nt][2] = __expf(sacc[nt][2] - m1n);
            sacc[nt][3] = __expf(sacc[nt][3] - m1n);
            s0 += sacc[nt][0] + sacc[nt][1];
            s1 += sacc[nt][2] + sacc[nt][3];
        }
        s0 += __shfl_xor_sync(0xffffffffu, s0, 1);
        s0 += __shfl_xor_sync(0xffffffffu, s0, 2);
        s1 += __shfl_xor_sync(0xffffffffu, s1, 1);
        s1 += __shfl_xor_sync(0xffffffffu, s1, 2);

        l0 = l0 * c0 + s0;
        l1 = l1 * c1 + s1;
        m0 = m0n;
        m1 = m1n;

        #pragma unroll
        for (int nt = 0; nt < 16; nt++) {
            oacc[nt][0] *= c0; oacc[nt][1] *= c0;
            oacc[nt][2] *= c1; oacc[nt][3] *= c1;
        }

        // ---- O += P V : V-frags via LDS.128 ----
        #pragma unroll
        for (int cc = 0; cc < 2; cc++) {
            uint32_t afrA[4], afrB[4];
            afrA[0] = packh2(sacc[4 * cc][0],     sacc[4 * cc][1]);
            afrA[1] = packh2(sacc[4 * cc][2],     sacc[4 * cc][3]);
            afrA[2] = packh2(sacc[4 * cc + 1][0], sacc[4 * cc + 1][1]);
            afrA[3] = packh2(sacc[4 * cc + 1][2], sacc[4 * cc + 1][3]);
            afrB[0] = packh2(sacc[4 * cc + 2][0], sacc[4 * cc + 2][1]);
            afrB[1] = packh2(sacc[4 * cc + 2][2], sacc[4 * cc + 2][3]);
            afrB[2] = packh2(sacc[4 * cc + 3][0], sacc[4 * cc + 3][1]);
            afrB[3] = packh2(sacc[4 * cc + 3][2], sacc[4 * cc + 3][3]);
            #pragma unroll
            for (int nt = 0; nt < 16; nt++) {
                const int n = nt * 8 + g;
                uint4 vb = V4[n * (VROW_W / 4) + cc * 4 + t];
                mma16(oacc[nt], afrA, vb.x, vb.y);
                mma16(oacc[nt], afrB, vb.z, vb.w);
            }
        }

        if (kt + 2 < nkt) {
            __syncthreads();
            issue_stage(kt + 2);
        }
    }

    const float inv0 = 1.0f / l0;
    const float inv1 = 1.0f / l1;
    float* og = out + ((size_t)b * TT + q0) * HH;
    #pragma unroll
    for (int nt = 0; nt < 16; nt++) {
        const int col = nt * 8 + 2 * t;
        *reinterpret_cast<float2*>(&og[(size_t)r0l * HH + col]) =
            make_float2(oacc[nt][0] * inv0, oacc[nt][1] * inv0);
        *reinterpret_cast<float2*>(&og[(size_t)r1l * HH + col]) =
            make_float2(oacc[nt][2] * inv1, oacc[nt][3] * inv1);
    }
}

// ===========================================================================
// Launch
// ===========================================================================
extern "C" void kernel_launch(void* const* d_in, const int* in_sizes, int n_in,
                              void* d_out, int out_size)
{
    const float* x  = (const float*)d_in[0];
    const float* Wq = (const float*)d_in[1];
    const float* Wk = (const float*)d_in[2];
    const float* Wv = (const float*)d_in[3];
    float* out = (float*)d_out;

    cudaFuncSetAttribute(qkv_fused_kernel,
                         cudaFuncAttributeMaxDynamicSharedMemorySize, QKV_SMEM);
    cudaFuncSetAttribute(attn_fa2_kernel,
                         cudaFuncAttributeMaxDynamicSharedMemorySize, ATTN_SMEM);

    conv_w_kernel<<<dim3(24, 3), 256>>>(Wq, Wk, Wv);
    qkv_fused_kernel<<<TT * BB / 128, 256, QKV_SMEM>>>(x);
    attn_fa2_kernel<<<dim3(TT / 64, BB), 128, ATTN_SMEM>>>(out);
}